// round 6
// baseline (speedup 1.0000x reference)
#include <cuda_runtime.h>
#include <cuda_bf16.h>
#include <math.h>
#include <stdint.h>

#define NN 50000
#define NE 640000
#define DH 128
#define NG 1024
#define NL 3
#define BN_EPS 1e-5f

#define SCAN_T 256
#define SCAN_NB ((NN + SCAN_T - 1) / SCAN_T)   // 196

__device__ __forceinline__ uint32_t smem_to_u32(const void* p) {
    uint32_t a;
    asm("{ .reg .u64 t; cvta.to.shared.u64 t, %1; cvt.u32.u64 %0, t; }" : "=r"(a) : "l"(p));
    return a;
}

// ---------------- scratch ----------------
__device__ int   g_deg[NN];
__device__ int   g_off[NN + 1];
__device__ int   g_cur[NN];
__device__ float g_dinv[NN];
__device__ int   g_csr[NE];
__device__ int   g_bsum[SCAN_NB];
__device__ int   g_boff[SCAN_NB];
__device__ float g_gbuf[(size_t)NN * DH];
__device__ float g_hag[(size_t)NN * DH];
__device__ float g_sum[NL * DH];
__device__ float g_sq[NL * DH];
__device__ float g_scale[NL * DH];
__device__ float g_shift[NL * DH];
__device__ int   g_cnt[NG];
__device__ unsigned short g_whi[NL * 16384];
__device__ unsigned short g_wlo[NL * 16384];

__device__ __forceinline__ float elu1(float v) {
    return v > 0.f ? v : (expf(v) - 1.f);
}

__device__ __forceinline__ int swz_off(int r, int kchunk) {
    return r * 256 + ((kchunk ^ (r & 7)) << 4);
}

// ---------------- launch 1: init everything + W convert ----------------
__global__ void k_init_all(const float* __restrict__ Ws) {
    int i = blockIdx.x * 256 + threadIdx.x;
    if (i < NN) g_deg[i] = 0;
    if (i < NL * DH) { g_sum[i] = 0.f; g_sq[i] = 0.f; }
    if (i < NG) g_cnt[i] = 0;
    if (i < NL * 16384) {
        int l = i >> 14;
        int rem = i & 16383;
        int n = rem & 127;
        int k = rem >> 7;
        float w = Ws[(size_t)l * 16384 + k * 128 + n];
        __nv_bfloat16 hi = __float2bfloat16(w);
        float lof = w - __bfloat162float(hi);
        __nv_bfloat16 lo = __float2bfloat16(lof);
        int off = swz_off(n, k >> 3) + (k & 7) * 2;
        int a = l * 16384 + (off >> 1);
        g_whi[a] = __bfloat16_as_ushort(hi);
        g_wlo[a] = __bfloat16_as_ushort(lo);
    }
}

// ---------------- launch 2: degree histogram + graph counts ----------------
__global__ void k_deg(const int* __restrict__ dst, const int* __restrict__ bidx) {
    int e = blockIdx.x * blockDim.x + threadIdx.x;
    if (e < NE) atomicAdd(&g_deg[dst[e]], 1);
    if (e < NN) atomicAdd(&g_cnt[bidx[e]], 1);
}

// ---------------- launch 3: dinv ----------------
__global__ void k_dinv() {
    int i = blockIdx.x * blockDim.x + threadIdx.x;
    if (i < NN) g_dinv[i] = rsqrtf((float)(g_deg[i] + 1));
}

// ---------------- scans ----------------
__global__ void __launch_bounds__(SCAN_T) k_bsum() {
    int i = blockIdx.x * SCAN_T + threadIdx.x;
    int v = (i < NN) ? g_deg[i] : 0;
    #pragma unroll
    for (int o = 16; o; o >>= 1) v += __shfl_down_sync(0xffffffffu, v, o);
    __shared__ int ws[SCAN_T / 32];
    if ((threadIdx.x & 31) == 0) ws[threadIdx.x >> 5] = v;
    __syncthreads();
    if (threadIdx.x < SCAN_T / 32) {
        int s = ws[threadIdx.x];
        #pragma unroll
        for (int o = SCAN_T / 64; o; o >>= 1) s += __shfl_down_sync(0xffu, s, o);
        if (threadIdx.x == 0) g_bsum[blockIdx.x] = s;
    }
}

__global__ void __launch_bounds__(256) k_bscan() {
    int tid = threadIdx.x;
    int lane = tid & 31, wid = tid >> 5;
    int v = (tid < SCAN_NB) ? g_bsum[tid] : 0;
    int incl = v;
    #pragma unroll
    for (int o = 1; o < 32; o <<= 1) {
        int t = __shfl_up_sync(0xffffffffu, incl, o);
        if (lane >= o) incl += t;
    }
    __shared__ int wtot[8];
    if (lane == 31) wtot[wid] = incl;
    __syncthreads();
    if (tid < 8) {
        int s = wtot[tid];
        int si = s;
        #pragma unroll
        for (int o = 1; o < 8; o <<= 1) {
            int t = __shfl_up_sync(0xffu, si, o);
            if (tid >= o) si += t;
        }
        wtot[tid] = si - s;
    }
    __syncthreads();
    incl += wtot[wid];
    if (tid < SCAN_NB) g_boff[tid] = incl - v;
    if (tid == 255) g_off[NN] = incl;
}

__global__ void __launch_bounds__(SCAN_T) k_lscan() {
    int tid = threadIdx.x;
    int lane = tid & 31, wid = tid >> 5;
    int i = blockIdx.x * SCAN_T + tid;
    int v = (i < NN) ? g_deg[i] : 0;
    int incl = v;
    #pragma unroll
    for (int o = 1; o < 32; o <<= 1) {
        int t = __shfl_up_sync(0xffffffffu, incl, o);
        if (lane >= o) incl += t;
    }
    __shared__ int wtot[SCAN_T / 32];
    if (lane == 31) wtot[wid] = incl;
    __syncthreads();
    if (tid < SCAN_T / 32) {
        int s = wtot[tid];
        int si = s;
        #pragma unroll
        for (int o = 1; o < SCAN_T / 32; o <<= 1) {
            int t = __shfl_up_sync(0xffu, si, o);
            if (tid >= o) si += t;
        }
        wtot[tid] = si - s;
    }
    __syncthreads();
    int excl = incl - v + wtot[wid] + g_boff[blockIdx.x];
    if (i < NN) {
        g_off[i] = excl;
        g_cur[i] = excl;
    }
}

__global__ void k_fill(const int* __restrict__ src, const int* __restrict__ dst) {
    int e = blockIdx.x * blockDim.x + threadIdx.x;
    if (e < NE) {
        int d = dst[e];
        int pos = atomicAdd(&g_cur[d], 1);
        g_csr[pos] = src[e];
    }
}

// ---------------- HMMA GEMM: g = dinv * (A' @ W) ----------------
// 128x128x128 block, 512 threads / 16 warps, warp tile 32x32, bf16 3-way split
#define SA_HI 0
#define SA_LO 32768
#define SB_HI 65536
#define SB_LO 98304
#define SM_TOTAL 131072

__device__ __forceinline__ void ldsm4(uint32_t& r0, uint32_t& r1, uint32_t& r2,
                                      uint32_t& r3, uint32_t addr) {
    asm volatile("ldmatrix.sync.aligned.m8n8.x4.shared.b16 {%0,%1,%2,%3}, [%4];"
                 : "=r"(r0), "=r"(r1), "=r"(r2), "=r"(r3) : "r"(addr));
}
__device__ __forceinline__ void mma16816(float* d, const uint32_t* a, const uint32_t* b) {
    asm volatile(
        "mma.sync.aligned.m16n8k16.row.col.f32.bf16.bf16.f32 "
        "{%0,%1,%2,%3}, {%4,%5,%6,%7}, {%8,%9}, {%0,%1,%2,%3};"
        : "+f"(d[0]), "+f"(d[1]), "+f"(d[2]), "+f"(d[3])
        : "r"(a[0]), "r"(a[1]), "r"(a[2]), "r"(a[3]), "r"(b[0]), "r"(b[1]));
}
#define CP_ASYNC16(dst, src) \
    asm volatile("cp.async.cg.shared.global [%0], [%1], 16;" :: "r"(dst), "l"(src))
#define CP_COMMIT() asm volatile("cp.async.commit_group;" ::: "memory")
#define CP_WAIT0() asm volatile("cp.async.wait_group 0;" ::: "memory")

__global__ void __launch_bounds__(512) k_gemm_tc(int layer, const float* __restrict__ x) {
    extern __shared__ char sm[];
    uint32_t sm_u = smem_to_u32(sm);
    int tid = threadIdx.x;
    int wid = tid >> 5, lane = tid & 31;

    // --- B tiles via cp.async (overlaps with A conversion below)
    {
        const char* wh = (const char*)(g_whi + layer * 16384) + tid * 16;
        const char* wl = (const char*)(g_wlo + layer * 16384) + tid * 16;
        uint32_t bh = sm_u + SB_HI + tid * 16;
        uint32_t bl = sm_u + SB_LO + tid * 16;
        #pragma unroll
        for (int i = 0; i < 4; ++i) {
            CP_ASYNC16(bh + i * 8192, wh + i * 8192);
            CP_ASYNC16(bl + i * 8192, wl + i * 8192);
        }
        CP_COMMIT();
    }

    // --- convert A' quarter-row per thread (fused BN+ELU for layer>0)
    {
        const float* A = (layer == 0) ? x : g_hag;
        const float* sc = g_scale + (layer > 0 ? (layer - 1) * DH : 0);
        const float* sh = g_shift + (layer > 0 ? (layer - 1) * DH : 0);
        int row = tid >> 2, quarter = tid & 3;
        int gr = blockIdx.x * 128 + row;
        if (gr < NN) {
            const float4* ap = (const float4*)(A + (size_t)gr * DH + quarter * 32);
            #pragma unroll
            for (int c8 = 0; c8 < 4; ++c8) {
                int kc = quarter * 4 + c8;
                float4 v0 = ap[c8 * 2];
                float4 v1 = ap[c8 * 2 + 1];
                float f[8] = {v0.x, v0.y, v0.z, v0.w, v1.x, v1.y, v1.z, v1.w};
                if (layer > 0) {
                    int k0 = kc * 8;
                    #pragma unroll
                    for (int c = 0; c < 8; ++c)
                        f[c] = elu1(fmaf(f[c], sc[k0 + c], sh[k0 + c]));
                }
                uint32_t hp[4], lp[4];
                #pragma unroll
                for (int p = 0; p < 4; ++p) {
                    __nv_bfloat16 h0 = __float2bfloat16(f[p * 2]);
                    __nv_bfloat16 h1 = __float2bfloat16(f[p * 2 + 1]);
                    __nv_bfloat16 l0 = __float2bfloat16(f[p * 2] - __bfloat162float(h0));
                    __nv_bfloat16 l1 = __float2bfloat16(f[p * 2 + 1] - __bfloat162float(h1));
                    hp[p] = (uint32_t)__bfloat16_as_ushort(h0) |
                            ((uint32_t)__bfloat16_as_ushort(h1) << 16);
                    lp[p] = (uint32_t)__bfloat16_as_ushort(l0) |
                            ((uint32_t)__bfloat16_as_ushort(l1) << 16);
                }
                int off = swz_off(row, kc);
                *(int4*)(sm + SA_HI + off) = make_int4(hp[0], hp[1], hp[2], hp[3]);
                *(int4*)(sm + SA_LO + off) = make_int4(lp[0], lp[1], lp[2], lp[3]);
            }
        } else {
            int4 z = make_int4(0, 0, 0, 0);
            #pragma unroll
            for (int c8 = 0; c8 < 4; ++c8) {
                int off = swz_off(row, quarter * 4 + c8);
                *(int4*)(sm + SA_HI + off) = z;
                *(int4*)(sm + SA_LO + off) = z;
            }
        }
    }
    CP_WAIT0();
    __syncthreads();

    // --- 16 warps: 4x4 grid of 32x32 warp tiles
    int warp_m = (wid & 3) * 32;
    int warp_n = (wid >> 2) * 32;

    float acc[2][4][4];
    #pragma unroll
    for (int i = 0; i < 2; ++i)
        #pragma unroll
        for (int j = 0; j < 4; ++j)
            #pragma unroll
            for (int c = 0; c < 4; ++c) acc[i][j][c] = 0.f;

    int sub = lane >> 3, l7 = lane & 7;
    int a_r0 = warp_m + (sub & 1) * 8 + l7;
    int a_cadd = sub >> 1;
    int b_nsel = (sub >> 1) * 8 + l7;
    int b_cadd = sub & 1;

    #pragma unroll
    for (int pass = 0; pass < 3; ++pass) {
        uint32_t aBase = sm_u + ((pass == 2) ? SA_LO : SA_HI);
        uint32_t bBase = sm_u + ((pass == 1) ? SB_LO : SB_HI);
        #pragma unroll
        for (int ks = 0; ks < 8; ++ks) {
            uint32_t a[2][4];
            #pragma unroll
            for (int mf = 0; mf < 2; ++mf) {
                int r = a_r0 + mf * 16;
                int kc = ks * 2 + a_cadd;
                ldsm4(a[mf][0], a[mf][1], a[mf][2], a[mf][3],
                      aBase + swz_off(r, kc));
            }
            uint32_t b[4][2];
            #pragma unroll
            for (int p = 0; p < 2; ++p) {
                int r = warp_n + p * 16 + b_nsel;
                int kc = ks * 2 + b_cadd;
                ldsm4(b[p * 2][0], b[p * 2][1], b[p * 2 + 1][0], b[p * 2 + 1][1],
                      bBase + swz_off(r, kc));
            }
            #pragma unroll
            for (int mf = 0; mf < 2; ++mf)
                #pragma unroll
                for (int nf = 0; nf < 4; ++nf)
                    mma16816(acc[mf][nf], a[mf], b[nf]);
        }
    }

    // --- epilogue
    int qr = lane >> 2, qc = (lane & 3) * 2;
    #pragma unroll
    for (int mf = 0; mf < 2; ++mf) {
        int r0 = blockIdx.x * 128 + warp_m + mf * 16 + qr;
        int r1 = r0 + 8;
        float d0 = (r0 < NN) ? g_dinv[r0] : 0.f;
        float d1 = (r1 < NN) ? g_dinv[r1] : 0.f;
        #pragma unroll
        for (int nf = 0; nf < 4; ++nf) {
            int col = warp_n + nf * 8 + qc;
            if (r0 < NN) {
                float2 o = make_float2(acc[mf][nf][0] * d0, acc[mf][nf][1] * d0);
                *(float2*)(g_gbuf + (size_t)r0 * DH + col) = o;
            }
            if (r1 < NN) {
                float2 o = make_float2(acc[mf][nf][2] * d1, acc[mf][nf][3] * d1);
                *(float2*)(g_gbuf + (size_t)r1 * DH + col) = o;
            }
        }
    }
}

// ---------------- aggregation: 4 nodes per warp, 32 nodes per block ----------
__global__ void __launch_bounds__(256) k_agg(int layer, const float* __restrict__ bias) {
    __shared__ float s_sum[DH];
    __shared__ float s_sq[DH];
    int tid = threadIdx.x;
    if (tid < DH) { s_sum[tid] = 0.f; s_sq[tid] = 0.f; }
    __syncthreads();

    int warp = tid >> 5, lane = tid & 31;
    int base = blockIdx.x * 32 + warp * 4;
    int f = lane * 4;
    float4 b = ((const float4*)bias)[lane];

    float ls0 = 0.f, ls1 = 0.f, ls2 = 0.f, ls3 = 0.f;
    float lq0 = 0.f, lq1 = 0.f, lq2 = 0.f, lq3 = 0.f;

    int nend = base + 4 < NN ? base + 4 : NN;
    for (int node = base; node < nend; ++node) {
        float4 a0 = *(const float4*)(g_gbuf + (size_t)node * DH + f);
        float4 a1 = make_float4(0.f, 0.f, 0.f, 0.f);
        int s = g_off[node], e2 = g_off[node + 1];
        int p = s;
        for (; p + 1 < e2; p += 2) {
            int s0 = g_csr[p];
            int s1 = g_csr[p + 1];
            float4 v0 = *(const float4*)(g_gbuf + (size_t)s0 * DH + f);
            float4 v1 = *(const float4*)(g_gbuf + (size_t)s1 * DH + f);
            a0.x += v0.x; a0.y += v0.y; a0.z += v0.z; a0.w += v0.w;
            a1.x += v1.x; a1.y += v1.y; a1.z += v1.z; a1.w += v1.w;
        }
        if (p < e2) {
            int s0 = g_csr[p];
            float4 v0 = *(const float4*)(g_gbuf + (size_t)s0 * DH + f);
            a0.x += v0.x; a0.y += v0.y; a0.z += v0.z; a0.w += v0.w;
        }
        float di = g_dinv[node];
        float4 h;
        h.x = fmaf(di, a0.x + a1.x, b.x);
        h.y = fmaf(di, a0.y + a1.y, b.y);
        h.z = fmaf(di, a0.z + a1.z, b.z);
        h.w = fmaf(di, a0.w + a1.w, b.w);
        *(float4*)(g_hag + (size_t)node * DH + f) = h;

        ls0 += h.x; lq0 += h.x * h.x;
        ls1 += h.y; lq1 += h.y * h.y;
        ls2 += h.z; lq2 += h.z * h.z;
        ls3 += h.w; lq3 += h.w * h.w;
    }
    atomicAdd(&s_sum[f + 0], ls0); atomicAdd(&s_sq[f + 0], lq0);
    atomicAdd(&s_sum[f + 1], ls1); atomicAdd(&s_sq[f + 1], lq1);
    atomicAdd(&s_sum[f + 2], ls2); atomicAdd(&s_sq[f + 2], lq2);
    atomicAdd(&s_sum[f + 3], ls3); atomicAdd(&s_sq[f + 3], lq3);
    __syncthreads();
    if (tid < DH) {
        atomicAdd(&g_sum[layer * DH + tid], s_sum[tid]);
        atomicAdd(&g_sq[layer * DH + tid], s_sq[tid]);
    }
}

// ---------------- BN finalize ----------------
__global__ void k_fin(int layer, const float* __restrict__ gamma,
                      const float* __restrict__ beta) {
    int h = threadIdx.x;
    float m = g_sum[layer * DH + h] * (1.f / NN);
    float var = g_sq[layer * DH + h] * (1.f / NN) - m * m;
    float rs = rsqrtf(var + BN_EPS);
    float sc = gamma[h] * rs;
    g_scale[layer * DH + h] = sc;
    g_shift[layer * DH + h] = beta[h] - m * sc;
}

// ---------------- pooling ----------------
__global__ void __launch_bounds__(256) k_pool(const int* __restrict__ bidx,
                                              float* __restrict__ out) {
    int tid = threadIdx.x;
    int warp = (blockIdx.x * 8 + (tid >> 5));
    int base = warp * 8;
    if (base >= NN) return;
    int lane = tid & 31;
    int f = lane * 4;
    const int L2 = (NL - 1) * DH;
    float s0 = g_scale[L2 + f], s1 = g_scale[L2 + f + 1],
          s2 = g_scale[L2 + f + 2], s3 = g_scale[L2 + f + 3];
    float t0 = g_shift[L2 + f], t1 = g_shift[L2 + f + 1],
          t2 = g_shift[L2 + f + 2], t3 = g_shift[L2 + f + 3];

    float a0 = 0.f, a1 = 0.f, a2 = 0.f, a3 = 0.f;
    int cur = bidx[base];
    int end = base + 8 < NN ? base + 8 : NN;
    for (int n = base; n < end; ++n) {
        int gi = bidx[n];
        if (gi != cur) {
            float* o = out + (size_t)cur * DH + f;
            atomicAdd(o + 0, a0); atomicAdd(o + 1, a1);
            atomicAdd(o + 2, a2); atomicAdd(o + 3, a3);
            a0 = a1 = a2 = a3 = 0.f;
            cur = gi;
        }
        float4 h = *(const float4*)(g_hag + (size_t)n * DH + f);
        a0 += elu1(fmaf(h.x, s0, t0));
        a1 += elu1(fmaf(h.y, s1, t1));
        a2 += elu1(fmaf(h.z, s2, t2));
        a3 += elu1(fmaf(h.w, s3, t3));
    }
    float* o = out + (size_t)cur * DH + f;
    atomicAdd(o + 0, a0); atomicAdd(o + 1, a1);
    atomicAdd(o + 2, a2); atomicAdd(o + 3, a3);
}

__global__ void k_div(float* __restrict__ out) {
    int i = blockIdx.x * blockDim.x + threadIdx.x;
    if (i < NG * DH) {
        float c = (float)g_cnt[i >> 7];
        out[i] = out[i] / fmaxf(c, 1.f);
    }
}

// ---------------- launch ----------------
extern "C" void kernel_launch(void* const* d_in, const int* in_sizes, int n_in,
                              void* d_out, int out_size) {
    const float* x      = (const float*)d_in[0];
    const float* Ws     = (const float*)d_in[1];
    const float* bs     = (const float*)d_in[2];
    const float* gammas = (const float*)d_in[3];
    const float* betas  = (const float*)d_in[4];
    const int*   ei     = (const int*)d_in[5];
    const int*   bidx   = (const int*)d_in[6];
    float*       out    = (float*)d_out;

    const int* src = ei;
    const int* dst = ei + NE;

    cudaFuncSetAttribute(k_gemm_tc, cudaFuncAttributeMaxDynamicSharedMemorySize, SM_TOTAL);

    int gemm_grid = (NN + 127) / 128;
    int agg_grid = (NN + 31) / 32;

    k_init_all<<<(NN + 255) / 256, 256>>>(Ws);          // 1
    k_deg<<<(NE + 255) / 256, 256>>>(dst, bidx);        // 2
    k_dinv<<<(NN + 255) / 256, 256>>>();                // 3
    k_gemm_tc<<<gemm_grid, 512, SM_TOTAL>>>(0, x);      // 4  <- ncu capture slot
    k_bsum<<<SCAN_NB, SCAN_T>>>();                      // 5
    k_bscan<<<1, 256>>>();                              // 6
    k_lscan<<<SCAN_NB, SCAN_T>>>();                     // 7
    k_fill<<<(NE + 255) / 256, 256>>>(src, dst);        // 8

    k_agg<<<agg_grid, 256>>>(0, bs);                    // 9
    k_fin<<<1, DH>>>(0, gammas, betas);
    for (int l = 1; l < NL; ++l) {
        k_gemm_tc<<<gemm_grid, 512, SM_TOTAL>>>(l, x);
        k_agg<<<agg_grid, 256>>>(l, bs + l * DH);
        k_fin<<<1, DH>>>(l, gammas + l * DH, betas + l * DH);
    }

    cudaMemsetAsync(d_out, 0, (size_t)NG * DH * sizeof(float));
    int pool_grid = (NN + 63) / 64;
    k_pool<<<pool_grid, 256>>>(bidx, out);
    k_div<<<(NG * DH + 255) / 256, 256>>>(out);
}

// round 7
// speedup vs baseline: 1.0620x; 1.0620x over previous
#include <cuda_runtime.h>
#include <cuda_bf16.h>
#include <math.h>
#include <stdint.h>

#define NN 50000
#define NE 640000
#define DH 128
#define NG 1024
#define NL 3
#define BN_EPS 1e-5f

#define SCAN_T 256
#define SCAN_NB ((NN + SCAN_T - 1) / SCAN_T)   // 196

__device__ __forceinline__ uint32_t smem_to_u32(const void* p) {
    uint32_t a;
    asm("{ .reg .u64 t; cvta.to.shared.u64 t, %1; cvt.u32.u64 %0, t; }" : "=r"(a) : "l"(p));
    return a;
}

// ---------------- scratch ----------------
__device__ int   g_deg[NN];
__device__ int   g_off[NN + 1];
__device__ int   g_cur[NN];
__device__ float g_dinv[NN];
__device__ int   g_csr[NE];
__device__ int   g_bsum[SCAN_NB];
__device__ int   g_boff[SCAN_NB];
__device__ float g_gbuf[(size_t)NN * DH];
__device__ float g_hag[(size_t)NN * DH];
__device__ float g_sum[NL * DH];
__device__ float g_sq[NL * DH];
__device__ float g_scale[NL * DH];
__device__ float g_shift[NL * DH];
__device__ int   g_cnt[NG];
__device__ unsigned short g_whi[NL * 16384];
__device__ unsigned short g_wlo[NL * 16384];

__device__ __forceinline__ float elu1(float v) {
    return v > 0.f ? v : (expf(v) - 1.f);
}

__device__ __forceinline__ int swz_off(int r, int kchunk) {
    return r * 256 + ((kchunk ^ (r & 7)) << 4);
}

// ---------------- launch 1: init everything + W convert ----------------
__global__ void k_init_all(const float* __restrict__ Ws) {
    int i = blockIdx.x * 256 + threadIdx.x;
    if (i < NN) g_deg[i] = 0;
    if (i < NL * DH) { g_sum[i] = 0.f; g_sq[i] = 0.f; }
    if (i < NG) g_cnt[i] = 0;
    if (i < NL * 16384) {
        int l = i >> 14;
        int rem = i & 16383;
        int n = rem & 127;
        int k = rem >> 7;
        float w = Ws[(size_t)l * 16384 + k * 128 + n];
        __nv_bfloat16 hi = __float2bfloat16(w);
        float lof = w - __bfloat162float(hi);
        __nv_bfloat16 lo = __float2bfloat16(lof);
        int off = swz_off(n, k >> 3) + (k & 7) * 2;
        int a = l * 16384 + (off >> 1);
        g_whi[a] = __bfloat16_as_ushort(hi);
        g_wlo[a] = __bfloat16_as_ushort(lo);
    }
}

// ---------------- launch 2: degree histogram + graph counts ----------------
__global__ void k_deg(const int* __restrict__ dst, const int* __restrict__ bidx) {
    int e = blockIdx.x * blockDim.x + threadIdx.x;
    if (e < NE) atomicAdd(&g_deg[dst[e]], 1);
    if (e < NN) atomicAdd(&g_cnt[bidx[e]], 1);
}

// ---------------- launch 3: dinv ----------------
__global__ void k_dinv() {
    int i = blockIdx.x * blockDim.x + threadIdx.x;
    if (i < NN) g_dinv[i] = rsqrtf((float)(g_deg[i] + 1));
}

// ---------------- scans ----------------
__global__ void __launch_bounds__(SCAN_T) k_bsum() {
    int i = blockIdx.x * SCAN_T + threadIdx.x;
    int v = (i < NN) ? g_deg[i] : 0;
    #pragma unroll
    for (int o = 16; o; o >>= 1) v += __shfl_down_sync(0xffffffffu, v, o);
    __shared__ int ws[SCAN_T / 32];
    if ((threadIdx.x & 31) == 0) ws[threadIdx.x >> 5] = v;
    __syncthreads();
    if (threadIdx.x < SCAN_T / 32) {
        int s = ws[threadIdx.x];
        #pragma unroll
        for (int o = SCAN_T / 64; o; o >>= 1) s += __shfl_down_sync(0xffu, s, o);
        if (threadIdx.x == 0) g_bsum[blockIdx.x] = s;
    }
}

__global__ void __launch_bounds__(256) k_bscan() {
    int tid = threadIdx.x;
    int lane = tid & 31, wid = tid >> 5;
    int v = (tid < SCAN_NB) ? g_bsum[tid] : 0;
    int incl = v;
    #pragma unroll
    for (int o = 1; o < 32; o <<= 1) {
        int t = __shfl_up_sync(0xffffffffu, incl, o);
        if (lane >= o) incl += t;
    }
    __shared__ int wtot[8];
    if (lane == 31) wtot[wid] = incl;
    __syncthreads();
    if (tid < 8) {
        int s = wtot[tid];
        int si = s;
        #pragma unroll
        for (int o = 1; o < 8; o <<= 1) {
            int t = __shfl_up_sync(0xffu, si, o);
            if (tid >= o) si += t;
        }
        wtot[tid] = si - s;
    }
    __syncthreads();
    incl += wtot[wid];
    if (tid < SCAN_NB) g_boff[tid] = incl - v;
    if (tid == 255) g_off[NN] = incl;
}

__global__ void __launch_bounds__(SCAN_T) k_lscan() {
    int tid = threadIdx.x;
    int lane = tid & 31, wid = tid >> 5;
    int i = blockIdx.x * SCAN_T + tid;
    int v = (i < NN) ? g_deg[i] : 0;
    int incl = v;
    #pragma unroll
    for (int o = 1; o < 32; o <<= 1) {
        int t = __shfl_up_sync(0xffffffffu, incl, o);
        if (lane >= o) incl += t;
    }
    __shared__ int wtot[SCAN_T / 32];
    if (lane == 31) wtot[wid] = incl;
    __syncthreads();
    if (tid < SCAN_T / 32) {
        int s = wtot[tid];
        int si = s;
        #pragma unroll
        for (int o = 1; o < SCAN_T / 32; o <<= 1) {
            int t = __shfl_up_sync(0xffu, si, o);
            if (tid >= o) si += t;
        }
        wtot[tid] = si - s;
    }
    __syncthreads();
    int excl = incl - v + wtot[wid] + g_boff[blockIdx.x];
    if (i < NN) {
        g_off[i] = excl;
        g_cur[i] = excl;
    }
}

__global__ void k_fill(const int* __restrict__ src, const int* __restrict__ dst) {
    int e = blockIdx.x * blockDim.x + threadIdx.x;
    if (e < NE) {
        int d = dst[e];
        int pos = atomicAdd(&g_cur[d], 1);
        g_csr[pos] = src[e];
    }
}

// ---------------- HMMA GEMM: g = dinv * (A' @ W) ----------------
// 128x128x128 block, 256 threads / 8 warps, warp tile 32x64,
// bf16 3-way split with merged passes (A_hi/B_hi fragment reuse)
#define SA_HI 0
#define SA_LO 32768
#define SB_HI 65536
#define SB_LO 98304
#define SM_TOTAL 131072

__device__ __forceinline__ void ldsm4(uint32_t& r0, uint32_t& r1, uint32_t& r2,
                                      uint32_t& r3, uint32_t addr) {
    asm volatile("ldmatrix.sync.aligned.m8n8.x4.shared.b16 {%0,%1,%2,%3}, [%4];"
                 : "=r"(r0), "=r"(r1), "=r"(r2), "=r"(r3) : "r"(addr));
}
__device__ __forceinline__ void mma16816(float* d, const uint32_t* a, const uint32_t* b) {
    asm volatile(
        "mma.sync.aligned.m16n8k16.row.col.f32.bf16.bf16.f32 "
        "{%0,%1,%2,%3}, {%4,%5,%6,%7}, {%8,%9}, {%0,%1,%2,%3};"
        : "+f"(d[0]), "+f"(d[1]), "+f"(d[2]), "+f"(d[3])
        : "r"(a[0]), "r"(a[1]), "r"(a[2]), "r"(a[3]), "r"(b[0]), "r"(b[1]));
}
#define CP_ASYNC16(dst, src) \
    asm volatile("cp.async.cg.shared.global [%0], [%1], 16;" :: "r"(dst), "l"(src))
#define CP_COMMIT() asm volatile("cp.async.commit_group;" ::: "memory")
#define CP_WAIT0() asm volatile("cp.async.wait_group 0;" ::: "memory")

__global__ void __launch_bounds__(256) k_gemm_tc(int layer, const float* __restrict__ x) {
    extern __shared__ char sm[];
    uint32_t sm_u = smem_to_u32(sm);
    int tid = threadIdx.x;
    int wid = tid >> 5, lane = tid & 31;

    // --- B tiles via cp.async (overlaps with A conversion below)
    {
        const char* wh = (const char*)(g_whi + layer * 16384) + tid * 16;
        const char* wl = (const char*)(g_wlo + layer * 16384) + tid * 16;
        uint32_t bh = sm_u + SB_HI + tid * 16;
        uint32_t bl = sm_u + SB_LO + tid * 16;
        #pragma unroll
        for (int i = 0; i < 8; ++i) {
            CP_ASYNC16(bh + i * 4096, wh + i * 4096);
            CP_ASYNC16(bl + i * 4096, wl + i * 4096);
        }
        CP_COMMIT();
    }

    // --- convert A' half-row per thread (fused BN+ELU for layer>0)
    {
        const float* A = (layer == 0) ? x : g_hag;
        const float* sc = g_scale + (layer > 0 ? (layer - 1) * DH : 0);
        const float* sh = g_shift + (layer > 0 ? (layer - 1) * DH : 0);
        int row = tid >> 1, half = tid & 1;
        int gr = blockIdx.x * 128 + row;
        if (gr < NN) {
            const float4* ap = (const float4*)(A + (size_t)gr * DH + half * 64);
            #pragma unroll
            for (int c8 = 0; c8 < 8; ++c8) {
                int kc = half * 8 + c8;
                float4 v0 = ap[c8 * 2];
                float4 v1 = ap[c8 * 2 + 1];
                float f[8] = {v0.x, v0.y, v0.z, v0.w, v1.x, v1.y, v1.z, v1.w};
                if (layer > 0) {
                    int k0 = kc * 8;
                    #pragma unroll
                    for (int c = 0; c < 8; ++c)
                        f[c] = elu1(fmaf(f[c], sc[k0 + c], sh[k0 + c]));
                }
                uint32_t hp[4], lp[4];
                #pragma unroll
                for (int p = 0; p < 4; ++p) {
                    __nv_bfloat16 h0 = __float2bfloat16(f[p * 2]);
                    __nv_bfloat16 h1 = __float2bfloat16(f[p * 2 + 1]);
                    __nv_bfloat16 l0 = __float2bfloat16(f[p * 2] - __bfloat162float(h0));
                    __nv_bfloat16 l1 = __float2bfloat16(f[p * 2 + 1] - __bfloat162float(h1));
                    hp[p] = (uint32_t)__bfloat16_as_ushort(h0) |
                            ((uint32_t)__bfloat16_as_ushort(h1) << 16);
                    lp[p] = (uint32_t)__bfloat16_as_ushort(l0) |
                            ((uint32_t)__bfloat16_as_ushort(l1) << 16);
                }
                int off = swz_off(row, kc);
                *(int4*)(sm + SA_HI + off) = make_int4(hp[0], hp[1], hp[2], hp[3]);
                *(int4*)(sm + SA_LO + off) = make_int4(lp[0], lp[1], lp[2], lp[3]);
            }
        } else {
            int4 z = make_int4(0, 0, 0, 0);
            #pragma unroll
            for (int c8 = 0; c8 < 8; ++c8) {
                int off = swz_off(row, half * 8 + c8);
                *(int4*)(sm + SA_HI + off) = z;
                *(int4*)(sm + SA_LO + off) = z;
            }
        }
    }
    CP_WAIT0();
    __syncthreads();

    // --- 8 warps: warp tile 32x64
    int warp_m = (wid & 3) * 32;
    int warp_n = (wid >> 2) * 64;

    float acc[2][8][4];
    #pragma unroll
    for (int i = 0; i < 2; ++i)
        #pragma unroll
        for (int j = 0; j < 8; ++j)
            #pragma unroll
            for (int c = 0; c < 4; ++c) acc[i][j][c] = 0.f;

    int sub = lane >> 3, l7 = lane & 7;
    int a_r0 = warp_m + (sub & 1) * 8 + l7;
    int a_cadd = sub >> 1;
    int b_nsel = (sub >> 1) * 8 + l7;
    int b_cadd = sub & 1;

    uint32_t aHi = sm_u + SA_HI, aLo = sm_u + SA_LO;
    uint32_t bHi = sm_u + SB_HI, bLo = sm_u + SB_LO;

    #pragma unroll
    for (int ks = 0; ks < 8; ++ks) {
        int a_kc = ks * 2 + a_cadd;
        int b_kc = ks * 2 + b_cadd;

        // A_hi fragments (reused for both B_hi and B_lo)
        uint32_t ah[2][4];
        #pragma unroll
        for (int mf = 0; mf < 2; ++mf)
            ldsm4(ah[mf][0], ah[mf][1], ah[mf][2], ah[mf][3],
                  aHi + swz_off(a_r0 + mf * 16, a_kc));

        // B_hi fragments (reused for both A_hi and A_lo)
        uint32_t bh[8][2];
        #pragma unroll
        for (int p = 0; p < 4; ++p)
            ldsm4(bh[p * 2][0], bh[p * 2][1], bh[p * 2 + 1][0], bh[p * 2 + 1][1],
                  bHi + swz_off(warp_n + p * 16 + b_nsel, b_kc));

        #pragma unroll
        for (int mf = 0; mf < 2; ++mf)
            #pragma unroll
            for (int nf = 0; nf < 8; ++nf)
                mma16816(acc[mf][nf], ah[mf], bh[nf]);

        // B_lo: A_hi x B_lo
        uint32_t bl[8][2];
        #pragma unroll
        for (int p = 0; p < 4; ++p)
            ldsm4(bl[p * 2][0], bl[p * 2][1], bl[p * 2 + 1][0], bl[p * 2 + 1][1],
                  bLo + swz_off(warp_n + p * 16 + b_nsel, b_kc));

        #pragma unroll
        for (int mf = 0; mf < 2; ++mf)
            #pragma unroll
            for (int nf = 0; nf < 8; ++nf)
                mma16816(acc[mf][nf], ah[mf], bl[nf]);

        // A_lo: A_lo x B_hi
        uint32_t al[2][4];
        #pragma unroll
        for (int mf = 0; mf < 2; ++mf)
            ldsm4(al[mf][0], al[mf][1], al[mf][2], al[mf][3],
                  aLo + swz_off(a_r0 + mf * 16, a_kc));

        #pragma unroll
        for (int mf = 0; mf < 2; ++mf)
            #pragma unroll
            for (int nf = 0; nf < 8; ++nf)
                mma16816(acc[mf][nf], al[mf], bh[nf]);
    }

    // --- epilogue
    int qr = lane >> 2, qc = (lane & 3) * 2;
    #pragma unroll
    for (int mf = 0; mf < 2; ++mf) {
        int r0 = blockIdx.x * 128 + warp_m + mf * 16 + qr;
        int r1 = r0 + 8;
        float d0 = (r0 < NN) ? g_dinv[r0] : 0.f;
        float d1 = (r1 < NN) ? g_dinv[r1] : 0.f;
        #pragma unroll
        for (int nf = 0; nf < 8; ++nf) {
            int col = warp_n + nf * 8 + qc;
            if (r0 < NN) {
                float2 o = make_float2(acc[mf][nf][0] * d0, acc[mf][nf][1] * d0);
                *(float2*)(g_gbuf + (size_t)r0 * DH + col) = o;
            }
            if (r1 < NN) {
                float2 o = make_float2(acc[mf][nf][2] * d1, acc[mf][nf][3] * d1);
                *(float2*)(g_gbuf + (size_t)r1 * DH + col) = o;
            }
        }
    }
}

// ---------------- aggregation: 4 nodes per warp, 32 nodes per block ----------
__global__ void __launch_bounds__(256) k_agg(int layer, const float* __restrict__ bias) {
    __shared__ float s_sum[DH];
    __shared__ float s_sq[DH];
    int tid = threadIdx.x;
    if (tid < DH) { s_sum[tid] = 0.f; s_sq[tid] = 0.f; }
    __syncthreads();

    int warp = tid >> 5, lane = tid & 31;
    int base = blockIdx.x * 32 + warp * 4;
    int f = lane * 4;
    float4 b = ((const float4*)bias)[lane];

    float ls0 = 0.f, ls1 = 0.f, ls2 = 0.f, ls3 = 0.f;
    float lq0 = 0.f, lq1 = 0.f, lq2 = 0.f, lq3 = 0.f;

    int nend = base + 4 < NN ? base + 4 : NN;
    for (int node = base; node < nend; ++node) {
        float4 a0 = *(const float4*)(g_gbuf + (size_t)node * DH + f);
        float4 a1 = make_float4(0.f, 0.f, 0.f, 0.f);
        int s = g_off[node], e2 = g_off[node + 1];
        int p = s;
        for (; p + 1 < e2; p += 2) {
            int s0 = g_csr[p];
            int s1 = g_csr[p + 1];
            float4 v0 = *(const float4*)(g_gbuf + (size_t)s0 * DH + f);
            float4 v1 = *(const float4*)(g_gbuf + (size_t)s1 * DH + f);
            a0.x += v0.x; a0.y += v0.y; a0.z += v0.z; a0.w += v0.w;
            a1.x += v1.x; a1.y += v1.y; a1.z += v1.z; a1.w += v1.w;
        }
        if (p < e2) {
            int s0 = g_csr[p];
            float4 v0 = *(const float4*)(g_gbuf + (size_t)s0 * DH + f);
            a0.x += v0.x; a0.y += v0.y; a0.z += v0.z; a0.w += v0.w;
        }
        float di = g_dinv[node];
        float4 h;
        h.x = fmaf(di, a0.x + a1.x, b.x);
        h.y = fmaf(di, a0.y + a1.y, b.y);
        h.z = fmaf(di, a0.z + a1.z, b.z);
        h.w = fmaf(di, a0.w + a1.w, b.w);
        *(float4*)(g_hag + (size_t)node * DH + f) = h;

        ls0 += h.x; lq0 += h.x * h.x;
        ls1 += h.y; lq1 += h.y * h.y;
        ls2 += h.z; lq2 += h.z * h.z;
        ls3 += h.w; lq3 += h.w * h.w;
    }
    atomicAdd(&s_sum[f + 0], ls0); atomicAdd(&s_sq[f + 0], lq0);
    atomicAdd(&s_sum[f + 1], ls1); atomicAdd(&s_sq[f + 1], lq1);
    atomicAdd(&s_sum[f + 2], ls2); atomicAdd(&s_sq[f + 2], lq2);
    atomicAdd(&s_sum[f + 3], ls3); atomicAdd(&s_sq[f + 3], lq3);
    __syncthreads();
    if (tid < DH) {
        atomicAdd(&g_sum[layer * DH + tid], s_sum[tid]);
        atomicAdd(&g_sq[layer * DH + tid], s_sq[tid]);
    }
}

// ---------------- BN finalize ----------------
__global__ void k_fin(int layer, const float* __restrict__ gamma,
                      const float* __restrict__ beta) {
    int h = threadIdx.x;
    float m = g_sum[layer * DH + h] * (1.f / NN);
    float var = g_sq[layer * DH + h] * (1.f / NN) - m * m;
    float rs = rsqrtf(var + BN_EPS);
    float sc = gamma[h] * rs;
    g_scale[layer * DH + h] = sc;
    g_shift[layer * DH + h] = beta[h] - m * sc;
}

// ---------------- pooling ----------------
__global__ void __launch_bounds__(256) k_pool(const int* __restrict__ bidx,
                                              float* __restrict__ out) {
    int tid = threadIdx.x;
    int warp = (blockIdx.x * 8 + (tid >> 5));
    int base = warp * 8;
    if (base >= NN) return;
    int lane = tid & 31;
    int f = lane * 4;
    const int L2 = (NL - 1) * DH;
    float s0 = g_scale[L2 + f], s1 = g_scale[L2 + f + 1],
          s2 = g_scale[L2 + f + 2], s3 = g_scale[L2 + f + 3];
    float t0 = g_shift[L2 + f], t1 = g_shift[L2 + f + 1],
          t2 = g_shift[L2 + f + 2], t3 = g_shift[L2 + f + 3];

    float a0 = 0.f, a1 = 0.f, a2 = 0.f, a3 = 0.f;
    int cur = bidx[base];
    int end = base + 8 < NN ? base + 8 : NN;
    for (int n = base; n < end; ++n) {
        int gi = bidx[n];
        if (gi != cur) {
            float* o = out + (size_t)cur * DH + f;
            atomicAdd(o + 0, a0); atomicAdd(o + 1, a1);
            atomicAdd(o + 2, a2); atomicAdd(o + 3, a3);
            a0 = a1 = a2 = a3 = 0.f;
            cur = gi;
        }
        float4 h = *(const float4*)(g_hag + (size_t)n * DH + f);
        a0 += elu1(fmaf(h.x, s0, t0));
        a1 += elu1(fmaf(h.y, s1, t1));
        a2 += elu1(fmaf(h.z, s2, t2));
        a3 += elu1(fmaf(h.w, s3, t3));
    }
    float* o = out + (size_t)cur * DH + f;
    atomicAdd(o + 0, a0); atomicAdd(o + 1, a1);
    atomicAdd(o + 2, a2); atomicAdd(o + 3, a3);
}

__global__ void k_div(float* __restrict__ out) {
    int i = blockIdx.x * blockDim.x + threadIdx.x;
    if (i < NG * DH) {
        float c = (float)g_cnt[i >> 7];
        out[i] = out[i] / fmaxf(c, 1.f);
    }
}

// ---------------- launch ----------------
extern "C" void kernel_launch(void* const* d_in, const int* in_sizes, int n_in,
                              void* d_out, int out_size) {
    const float* x      = (const float*)d_in[0];
    const float* Ws     = (const float*)d_in[1];
    const float* bs     = (const float*)d_in[2];
    const float* gammas = (const float*)d_in[3];
    const float* betas  = (const float*)d_in[4];
    const int*   ei     = (const int*)d_in[5];
    const int*   bidx   = (const int*)d_in[6];
    float*       out    = (float*)d_out;

    const int* src = ei;
    const int* dst = ei + NE;

    cudaFuncSetAttribute(k_gemm_tc, cudaFuncAttributeMaxDynamicSharedMemorySize, SM_TOTAL);

    int gemm_grid = (NN + 127) / 128;
    int agg_grid = (NN + 31) / 32;

    k_init_all<<<(NN + 255) / 256, 256>>>(Ws);          // 1
    k_deg<<<(NE + 255) / 256, 256>>>(dst, bidx);        // 2
    k_dinv<<<(NN + 255) / 256, 256>>>();                // 3
    k_gemm_tc<<<gemm_grid, 256, SM_TOTAL>>>(0, x);      // 4  <- ncu capture slot
    k_bsum<<<SCAN_NB, SCAN_T>>>();                      // 5
    k_bscan<<<1, 256>>>();                              // 6
    k_lscan<<<SCAN_NB, SCAN_T>>>();                     // 7
    k_fill<<<(NE + 255) / 256, 256>>>(src, dst);        // 8

    k_agg<<<agg_grid, 256>>>(0, bs);                    // 9
    k_fin<<<1, DH>>>(0, gammas, betas);
    for (int l = 1; l < NL; ++l) {
        k_gemm_tc<<<gemm_grid, 256, SM_TOTAL>>>(l, x);
        k_agg<<<agg_grid, 256>>>(l, bs + l * DH);
        k_fin<<<1, DH>>>(l, gammas + l * DH, betas + l * DH);
    }

    cudaMemsetAsync(d_out, 0, (size_t)NG * DH * sizeof(float));
    int pool_grid = (NN + 63) / 64;
    k_pool<<<pool_grid, 256>>>(bidx, out);
    k_div<<<(NG * DH + 255) / 256, 256>>>(out);
}

// round 8
// speedup vs baseline: 1.1080x; 1.0433x over previous
#include <cuda_runtime.h>
#include <cuda_bf16.h>
#include <math.h>
#include <stdint.h>

#define NN 50000
#define NE 640000
#define DH 128
#define NG 1024
#define NL 3
#define BN_EPS 1e-5f

#define SCAN_T 256
#define SCAN_NB ((NN + SCAN_T - 1) / SCAN_T)   // 196

__device__ __forceinline__ uint32_t smem_to_u32(const void* p) {
    uint32_t a;
    asm("{ .reg .u64 t; cvta.to.shared.u64 t, %1; cvt.u32.u64 %0, t; }" : "=r"(a) : "l"(p));
    return a;
}

// ---------------- scratch ----------------
__device__ int   g_deg[NN];
__device__ int   g_off[NN + 1];
__device__ int   g_cur[NN];
__device__ float g_dinv[NN];
__device__ int   g_csr[NE];
__device__ int   g_bsum[SCAN_NB];
__device__ int   g_boff[SCAN_NB];
__device__ float g_gbuf[(size_t)NN * DH];
__device__ float g_hag[(size_t)NN * DH];
__device__ float g_sum[NL * DH];
__device__ float g_sq[NL * DH];
__device__ float g_scale[NL * DH];
__device__ float g_shift[NL * DH];
__device__ int   g_cnt[NG];
// W^T bf16 hi/lo; per layer two 16KB slabs (k-halves), swizzled within slab
__device__ unsigned short g_whi[NL * 16384];
__device__ unsigned short g_wlo[NL * 16384];

__device__ __forceinline__ float elu1(float v) {
    return v > 0.f ? v : (expf(v) - 1.f);
}

// swizzled byte offset within a 128row x 64k bf16 (16KB) slab
__device__ __forceinline__ int swz64(int r, int kchunk) {
    return r * 128 + ((kchunk ^ (r & 7)) << 4);
}

// ---------------- launch 1: init everything + W convert ----------------
__global__ void k_init_all(const float* __restrict__ Ws) {
    int i = blockIdx.x * 256 + threadIdx.x;
    if (i < NN) g_deg[i] = 0;
    if (i < NL * DH) { g_sum[i] = 0.f; g_sq[i] = 0.f; }
    if (i < NG) g_cnt[i] = 0;
    if (i < NL * 16384) {
        int l = i >> 14;
        int rem = i & 16383;
        int n = rem & 127;
        int k = rem >> 7;
        float w = Ws[(size_t)l * 16384 + k * 128 + n];
        __nv_bfloat16 hi = __float2bfloat16(w);
        float lof = w - __bfloat162float(hi);
        __nv_bfloat16 lo = __float2bfloat16(lof);
        int half = k >> 6;
        int lc = (k & 63) >> 3;
        int off = swz64(n, lc) + (k & 7) * 2;
        int a = l * 16384 + half * 8192 + (off >> 1);
        g_whi[a] = __bfloat16_as_ushort(hi);
        g_wlo[a] = __bfloat16_as_ushort(lo);
    }
}

// ---------------- launch 2: degree histogram + graph counts ----------------
__global__ void k_deg(const int* __restrict__ dst, const int* __restrict__ bidx) {
    int e = blockIdx.x * blockDim.x + threadIdx.x;
    if (e < NE) atomicAdd(&g_deg[dst[e]], 1);
    if (e < NN) atomicAdd(&g_cnt[bidx[e]], 1);
}

// ---------------- launch 3: dinv ----------------
__global__ void k_dinv() {
    int i = blockIdx.x * blockDim.x + threadIdx.x;
    if (i < NN) g_dinv[i] = rsqrtf((float)(g_deg[i] + 1));
}

// ---------------- scans ----------------
__global__ void __launch_bounds__(SCAN_T) k_bsum() {
    int i = blockIdx.x * SCAN_T + threadIdx.x;
    int v = (i < NN) ? g_deg[i] : 0;
    #pragma unroll
    for (int o = 16; o; o >>= 1) v += __shfl_down_sync(0xffffffffu, v, o);
    __shared__ int ws[SCAN_T / 32];
    if ((threadIdx.x & 31) == 0) ws[threadIdx.x >> 5] = v;
    __syncthreads();
    if (threadIdx.x < SCAN_T / 32) {
        int s = ws[threadIdx.x];
        #pragma unroll
        for (int o = SCAN_T / 64; o; o >>= 1) s += __shfl_down_sync(0xffu, s, o);
        if (threadIdx.x == 0) g_bsum[blockIdx.x] = s;
    }
}

__global__ void __launch_bounds__(256) k_bscan() {
    int tid = threadIdx.x;
    int lane = tid & 31, wid = tid >> 5;
    int v = (tid < SCAN_NB) ? g_bsum[tid] : 0;
    int incl = v;
    #pragma unroll
    for (int o = 1; o < 32; o <<= 1) {
        int t = __shfl_up_sync(0xffffffffu, incl, o);
        if (lane >= o) incl += t;
    }
    __shared__ int wtot[8];
    if (lane == 31) wtot[wid] = incl;
    __syncthreads();
    if (tid < 8) {
        int s = wtot[tid];
        int si = s;
        #pragma unroll
        for (int o = 1; o < 8; o <<= 1) {
            int t = __shfl_up_sync(0xffu, si, o);
            if (tid >= o) si += t;
        }
        wtot[tid] = si - s;
    }
    __syncthreads();
    incl += wtot[wid];
    if (tid < SCAN_NB) g_boff[tid] = incl - v;
    if (tid == 255) g_off[NN] = incl;
}

__global__ void __launch_bounds__(SCAN_T) k_lscan() {
    int tid = threadIdx.x;
    int lane = tid & 31, wid = tid >> 5;
    int i = blockIdx.x * SCAN_T + tid;
    int v = (i < NN) ? g_deg[i] : 0;
    int incl = v;
    #pragma unroll
    for (int o = 1; o < 32; o <<= 1) {
        int t = __shfl_up_sync(0xffffffffu, incl, o);
        if (lane >= o) incl += t;
    }
    __shared__ int wtot[SCAN_T / 32];
    if (lane == 31) wtot[wid] = incl;
    __syncthreads();
    if (tid < SCAN_T / 32) {
        int s = wtot[tid];
        int si = s;
        #pragma unroll
        for (int o = 1; o < SCAN_T / 32; o <<= 1) {
            int t = __shfl_up_sync(0xffu, si, o);
            if (tid >= o) si += t;
        }
        wtot[tid] = si - s;
    }
    __syncthreads();
    int excl = incl - v + wtot[wid] + g_boff[blockIdx.x];
    if (i < NN) {
        g_off[i] = excl;
        g_cur[i] = excl;
    }
}

__global__ void k_fill(const int* __restrict__ src, const int* __restrict__ dst) {
    int e = blockIdx.x * blockDim.x + threadIdx.x;
    if (e < NE) {
        int d = dst[e];
        int pos = atomicAdd(&g_cur[d], 1);
        g_csr[pos] = src[e];
    }
}

// ---------------- HMMA GEMM: g = dinv * (A' @ W) ----------------
// 128x128 block, K staged in two 64-wide halves through 64KB smem -> 2 CTA/SM.
// 256 threads / 8 warps, warp tile 32x64, bf16 3-way split merged passes.
#define SA_HI 0
#define SA_LO 16384
#define SB_HI 32768
#define SB_LO 49152
#define SM_TOTAL 65536

__device__ __forceinline__ void ldsm4(uint32_t& r0, uint32_t& r1, uint32_t& r2,
                                      uint32_t& r3, uint32_t addr) {
    asm volatile("ldmatrix.sync.aligned.m8n8.x4.shared.b16 {%0,%1,%2,%3}, [%4];"
                 : "=r"(r0), "=r"(r1), "=r"(r2), "=r"(r3) : "r"(addr));
}
__device__ __forceinline__ void mma16816(float* d, const uint32_t* a, const uint32_t* b) {
    asm volatile(
        "mma.sync.aligned.m16n8k16.row.col.f32.bf16.bf16.f32 "
        "{%0,%1,%2,%3}, {%4,%5,%6,%7}, {%8,%9}, {%0,%1,%2,%3};"
        : "+f"(d[0]), "+f"(d[1]), "+f"(d[2]), "+f"(d[3])
        : "r"(a[0]), "r"(a[1]), "r"(a[2]), "r"(a[3]), "r"(b[0]), "r"(b[1]));
}
#define CP_ASYNC16(dst, src) \
    asm volatile("cp.async.cg.shared.global [%0], [%1], 16;" :: "r"(dst), "l"(src))
#define CP_COMMIT() asm volatile("cp.async.commit_group;" ::: "memory")
#define CP_WAIT0() asm volatile("cp.async.wait_group 0;" ::: "memory")

__global__ void __launch_bounds__(256, 2) k_gemm_tc(int layer, const float* __restrict__ x) {
    extern __shared__ char sm[];
    uint32_t sm_u = smem_to_u32(sm);
    int tid = threadIdx.x;
    int wid = tid >> 5, lane = tid & 31;

    const float* A = (layer == 0) ? x : g_hag;
    const float* sc = g_scale + (layer > 0 ? (layer - 1) * DH : 0);
    const float* sh = g_shift + (layer > 0 ? (layer - 1) * DH : 0);

    int warp_m = (wid & 3) * 32;
    int warp_n = (wid >> 2) * 64;

    float acc[2][8][4];
    #pragma unroll
    for (int i = 0; i < 2; ++i)
        #pragma unroll
        for (int j = 0; j < 8; ++j)
            #pragma unroll
            for (int c = 0; c < 4; ++c) acc[i][j][c] = 0.f;

    int sub = lane >> 3, l7 = lane & 7;
    int a_r0 = warp_m + (sub & 1) * 8 + l7;
    int a_cadd = sub >> 1;
    int b_nsel = (sub >> 1) * 8 + l7;
    int b_cadd = sub & 1;

    int row = tid >> 1, hq = tid & 1;   // conversion assignment
    int gr = blockIdx.x * 128 + row;

    #pragma unroll
    for (int half = 0; half < 2; ++half) {
        // --- B slab (16KB hi + 16KB lo) via cp.async
        {
            const char* wh = (const char*)(g_whi + layer * 16384 + half * 8192) + tid * 16;
            const char* wl = (const char*)(g_wlo + layer * 16384 + half * 8192) + tid * 16;
            uint32_t bh = sm_u + SB_HI + tid * 16;
            uint32_t bl = sm_u + SB_LO + tid * 16;
            #pragma unroll
            for (int i = 0; i < 4; ++i) {
                CP_ASYNC16(bh + i * 4096, wh + i * 4096);
                CP_ASYNC16(bl + i * 4096, wl + i * 4096);
            }
            CP_COMMIT();
        }
        // --- convert A' (32 floats per thread) for this k-half
        if (gr < NN) {
            const float4* ap = (const float4*)(A + (size_t)gr * DH + half * 64 + hq * 32);
            #pragma unroll
            for (int c8 = 0; c8 < 4; ++c8) {
                int lc = hq * 4 + c8;            // local kchunk 0..7
                float4 v0 = ap[c8 * 2];
                float4 v1 = ap[c8 * 2 + 1];
                float f[8] = {v0.x, v0.y, v0.z, v0.w, v1.x, v1.y, v1.z, v1.w};
                if (layer > 0) {
                    int k0 = half * 64 + lc * 8;
                    #pragma unroll
                    for (int c = 0; c < 8; ++c)
                        f[c] = elu1(fmaf(f[c], sc[k0 + c], sh[k0 + c]));
                }
                uint32_t hp[4], lp[4];
                #pragma unroll
                for (int p = 0; p < 4; ++p) {
                    __nv_bfloat16 h0 = __float2bfloat16(f[p * 2]);
                    __nv_bfloat16 h1 = __float2bfloat16(f[p * 2 + 1]);
                    __nv_bfloat16 l0 = __float2bfloat16(f[p * 2] - __bfloat162float(h0));
                    __nv_bfloat16 l1 = __float2bfloat16(f[p * 2 + 1] - __bfloat162float(h1));
                    hp[p] = (uint32_t)__bfloat16_as_ushort(h0) |
                            ((uint32_t)__bfloat16_as_ushort(h1) << 16);
                    lp[p] = (uint32_t)__bfloat16_as_ushort(l0) |
                            ((uint32_t)__bfloat16_as_ushort(l1) << 16);
                }
                int off = swz64(row, lc);
                *(int4*)(sm + SA_HI + off) = make_int4(hp[0], hp[1], hp[2], hp[3]);
                *(int4*)(sm + SA_LO + off) = make_int4(lp[0], lp[1], lp[2], lp[3]);
            }
        } else {
            int4 z = make_int4(0, 0, 0, 0);
            #pragma unroll
            for (int c8 = 0; c8 < 4; ++c8) {
                int off = swz64(row, hq * 4 + c8);
                *(int4*)(sm + SA_HI + off) = z;
                *(int4*)(sm + SA_LO + off) = z;
            }
        }
        CP_WAIT0();
        __syncthreads();

        // --- mainloop for this half: 4 k-steps, merged 3-pass split
        uint32_t aHi = sm_u + SA_HI, aLo = sm_u + SA_LO;
        uint32_t bHi = sm_u + SB_HI, bLo = sm_u + SB_LO;
        #pragma unroll
        for (int ks = 0; ks < 4; ++ks) {
            int a_kc = ks * 2 + a_cadd;
            int b_kc = ks * 2 + b_cadd;

            uint32_t ah[2][4];
            #pragma unroll
            for (int mf = 0; mf < 2; ++mf)
                ldsm4(ah[mf][0], ah[mf][1], ah[mf][2], ah[mf][3],
                      aHi + swz64(a_r0 + mf * 16, a_kc));

            uint32_t bh[8][2];
            #pragma unroll
            for (int p = 0; p < 4; ++p)
                ldsm4(bh[p * 2][0], bh[p * 2][1], bh[p * 2 + 1][0], bh[p * 2 + 1][1],
                      bHi + swz64(warp_n + p * 16 + b_nsel, b_kc));

            #pragma unroll
            for (int mf = 0; mf < 2; ++mf)
                #pragma unroll
                for (int nf = 0; nf < 8; ++nf)
                    mma16816(acc[mf][nf], ah[mf], bh[nf]);

            uint32_t bl[8][2];
            #pragma unroll
            for (int p = 0; p < 4; ++p)
                ldsm4(bl[p * 2][0], bl[p * 2][1], bl[p * 2 + 1][0], bl[p * 2 + 1][1],
                      bLo + swz64(warp_n + p * 16 + b_nsel, b_kc));

            #pragma unroll
            for (int mf = 0; mf < 2; ++mf)
                #pragma unroll
                for (int nf = 0; nf < 8; ++nf)
                    mma16816(acc[mf][nf], ah[mf], bl[nf]);

            uint32_t al[2][4];
            #pragma unroll
            for (int mf = 0; mf < 2; ++mf)
                ldsm4(al[mf][0], al[mf][1], al[mf][2], al[mf][3],
                      aLo + swz64(a_r0 + mf * 16, a_kc));

            #pragma unroll
            for (int mf = 0; mf < 2; ++mf)
                #pragma unroll
                for (int nf = 0; nf < 8; ++nf)
                    mma16816(acc[mf][nf], al[mf], bh[nf]);
        }
        if (half == 0) __syncthreads();   // all reads done before overwrite
    }

    // --- epilogue
    int qr = lane >> 2, qc = (lane & 3) * 2;
    #pragma unroll
    for (int mf = 0; mf < 2; ++mf) {
        int r0 = blockIdx.x * 128 + warp_m + mf * 16 + qr;
        int r1 = r0 + 8;
        float d0 = (r0 < NN) ? g_dinv[r0] : 0.f;
        float d1 = (r1 < NN) ? g_dinv[r1] : 0.f;
        #pragma unroll
        for (int nf = 0; nf < 8; ++nf) {
            int col = warp_n + nf * 8 + qc;
            if (r0 < NN) {
                float2 o = make_float2(acc[mf][nf][0] * d0, acc[mf][nf][1] * d0);
                *(float2*)(g_gbuf + (size_t)r0 * DH + col) = o;
            }
            if (r1 < NN) {
                float2 o = make_float2(acc[mf][nf][2] * d1, acc[mf][nf][3] * d1);
                *(float2*)(g_gbuf + (size_t)r1 * DH + col) = o;
            }
        }
    }
}

// ---------------- aggregation: 4 nodes per warp, 32 nodes per block ----------
__global__ void __launch_bounds__(256) k_agg(int layer, const float* __restrict__ bias) {
    __shared__ float s_sum[DH];
    __shared__ float s_sq[DH];
    int tid = threadIdx.x;
    if (tid < DH) { s_sum[tid] = 0.f; s_sq[tid] = 0.f; }
    __syncthreads();

    int warp = tid >> 5, lane = tid & 31;
    int base = blockIdx.x * 32 + warp * 4;
    int f = lane * 4;
    float4 b = ((const float4*)bias)[lane];

    float ls0 = 0.f, ls1 = 0.f, ls2 = 0.f, ls3 = 0.f;
    float lq0 = 0.f, lq1 = 0.f, lq2 = 0.f, lq3 = 0.f;

    int nend = base + 4 < NN ? base + 4 : NN;
    for (int node = base; node < nend; ++node) {
        float4 a0 = *(const float4*)(g_gbuf + (size_t)node * DH + f);
        float4 a1 = make_float4(0.f, 0.f, 0.f, 0.f);
        int s = g_off[node], e2 = g_off[node + 1];
        int p = s;
        for (; p + 1 < e2; p += 2) {
            int s0 = g_csr[p];
            int s1 = g_csr[p + 1];
            float4 v0 = *(const float4*)(g_gbuf + (size_t)s0 * DH + f);
            float4 v1 = *(const float4*)(g_gbuf + (size_t)s1 * DH + f);
            a0.x += v0.x; a0.y += v0.y; a0.z += v0.z; a0.w += v0.w;
            a1.x += v1.x; a1.y += v1.y; a1.z += v1.z; a1.w += v1.w;
        }
        if (p < e2) {
            int s0 = g_csr[p];
            float4 v0 = *(const float4*)(g_gbuf + (size_t)s0 * DH + f);
            a0.x += v0.x; a0.y += v0.y; a0.z += v0.z; a0.w += v0.w;
        }
        float di = g_dinv[node];
        float4 h;
        h.x = fmaf(di, a0.x + a1.x, b.x);
        h.y = fmaf(di, a0.y + a1.y, b.y);
        h.z = fmaf(di, a0.z + a1.z, b.z);
        h.w = fmaf(di, a0.w + a1.w, b.w);
        *(float4*)(g_hag + (size_t)node * DH + f) = h;

        ls0 += h.x; lq0 += h.x * h.x;
        ls1 += h.y; lq1 += h.y * h.y;
        ls2 += h.z; lq2 += h.z * h.z;
        ls3 += h.w; lq3 += h.w * h.w;
    }
    atomicAdd(&s_sum[f + 0], ls0); atomicAdd(&s_sq[f + 0], lq0);
    atomicAdd(&s_sum[f + 1], ls1); atomicAdd(&s_sq[f + 1], lq1);
    atomicAdd(&s_sum[f + 2], ls2); atomicAdd(&s_sq[f + 2], lq2);
    atomicAdd(&s_sum[f + 3], ls3); atomicAdd(&s_sq[f + 3], lq3);
    __syncthreads();
    if (tid < DH) {
        atomicAdd(&g_sum[layer * DH + tid], s_sum[tid]);
        atomicAdd(&g_sq[layer * DH + tid], s_sq[tid]);
    }
}

// ---------------- BN finalize ----------------
__global__ void k_fin(int layer, const float* __restrict__ gamma,
                      const float* __restrict__ beta) {
    int h = threadIdx.x;
    float m = g_sum[layer * DH + h] * (1.f / NN);
    float var = g_sq[layer * DH + h] * (1.f / NN) - m * m;
    float rs = rsqrtf(var + BN_EPS);
    float sc = gamma[h] * rs;
    g_scale[layer * DH + h] = sc;
    g_shift[layer * DH + h] = beta[h] - m * sc;
}

// ---------------- pooling ----------------
__global__ void __launch_bounds__(256) k_pool(const int* __restrict__ bidx,
                                              float* __restrict__ out) {
    int tid = threadIdx.x;
    int warp = (blockIdx.x * 8 + (tid >> 5));
    int base = warp * 8;
    if (base >= NN) return;
    int lane = tid & 31;
    int f = lane * 4;
    const int L2 = (NL - 1) * DH;
    float s0 = g_scale[L2 + f], s1 = g_scale[L2 + f + 1],
          s2 = g_scale[L2 + f + 2], s3 = g_scale[L2 + f + 3];
    float t0 = g_shift[L2 + f], t1 = g_shift[L2 + f + 1],
          t2 = g_shift[L2 + f + 2], t3 = g_shift[L2 + f + 3];

    float a0 = 0.f, a1 = 0.f, a2 = 0.f, a3 = 0.f;
    int cur = bidx[base];
    int end = base + 8 < NN ? base + 8 : NN;
    for (int n = base; n < end; ++n) {
        int gi = bidx[n];
        if (gi != cur) {
            float* o = out + (size_t)cur * DH + f;
            atomicAdd(o + 0, a0); atomicAdd(o + 1, a1);
            atomicAdd(o + 2, a2); atomicAdd(o + 3, a3);
            a0 = a1 = a2 = a3 = 0.f;
            cur = gi;
        }
        float4 h = *(const float4*)(g_hag + (size_t)n * DH + f);
        a0 += elu1(fmaf(h.x, s0, t0));
        a1 += elu1(fmaf(h.y, s1, t1));
        a2 += elu1(fmaf(h.z, s2, t2));
        a3 += elu1(fmaf(h.w, s3, t3));
    }
    float* o = out + (size_t)cur * DH + f;
    atomicAdd(o + 0, a0); atomicAdd(o + 1, a1);
    atomicAdd(o + 2, a2); atomicAdd(o + 3, a3);
}

__global__ void k_div(float* __restrict__ out) {
    int i = blockIdx.x * blockDim.x + threadIdx.x;
    if (i < NG * DH) {
        float c = (float)g_cnt[i >> 7];
        out[i] = out[i] / fmaxf(c, 1.f);
    }
}

// ---------------- launch ----------------
extern "C" void kernel_launch(void* const* d_in, const int* in_sizes, int n_in,
                              void* d_out, int out_size) {
    const float* x      = (const float*)d_in[0];
    const float* Ws     = (const float*)d_in[1];
    const float* bs     = (const float*)d_in[2];
    const float* gammas = (const float*)d_in[3];
    const float* betas  = (const float*)d_in[4];
    const int*   ei     = (const int*)d_in[5];
    const int*   bidx   = (const int*)d_in[6];
    float*       out    = (float*)d_out;

    const int* src = ei;
    const int* dst = ei + NE;

    cudaFuncSetAttribute(k_gemm_tc, cudaFuncAttributeMaxDynamicSharedMemorySize, SM_TOTAL);

    int gemm_grid = (NN + 127) / 128;
    int agg_grid = (NN + 31) / 32;

    k_init_all<<<(NN + 255) / 256, 256>>>(Ws);          // 1
    k_deg<<<(NE + 255) / 256, 256>>>(dst, bidx);        // 2
    k_dinv<<<(NN + 255) / 256, 256>>>();                // 3
    k_gemm_tc<<<gemm_grid, 256, SM_TOTAL>>>(0, x);      // 4  <- ncu capture slot
    k_bsum<<<SCAN_NB, SCAN_T>>>();                      // 5
    k_bscan<<<1, 256>>>();                              // 6
    k_lscan<<<SCAN_NB, SCAN_T>>>();                     // 7
    k_fill<<<(NE + 255) / 256, 256>>>(src, dst);        // 8

    k_agg<<<agg_grid, 256>>>(0, bs);                    // 9
    k_fin<<<1, DH>>>(0, gammas, betas);
    for (int l = 1; l < NL; ++l) {
        k_gemm_tc<<<gemm_grid, 256, SM_TOTAL>>>(l, x);
        k_agg<<<agg_grid, 256>>>(l, bs + l * DH);
        k_fin<<<1, DH>>>(l, gammas + l * DH, betas + l * DH);
    }

    cudaMemsetAsync(d_out, 0, (size_t)NG * DH * sizeof(float));
    int pool_grid = (NN + 63) / 64;
    k_pool<<<pool_grid, 256>>>(bidx, out);
    k_div<<<(NG * DH + 255) / 256, 256>>>(out);
}

// round 9
// speedup vs baseline: 1.3187x; 1.1901x over previous
#include <cuda_runtime.h>
#include <cuda_bf16.h>
#include <cuda_fp16.h>
#include <math.h>
#include <stdint.h>

#define NN 50000
#define NE 640000
#define DH 128
#define NG 1024
#define NL 3
#define BN_EPS 1e-5f

#define SCAN_T 256
#define SCAN_NB ((NN + SCAN_T - 1) / SCAN_T)   // 196

__device__ __forceinline__ uint32_t smem_to_u32(const void* p) {
    uint32_t a;
    asm("{ .reg .u64 t; cvta.to.shared.u64 t, %1; cvt.u32.u64 %0, t; }" : "=r"(a) : "l"(p));
    return a;
}

// ---------------- scratch ----------------
__device__ int   g_deg[NN];
__device__ int   g_off[NN + 1];
__device__ int   g_cur[NN];
__device__ float g_dinv[NN];
__device__ int   g_csr[NE];
__device__ int   g_bsum[SCAN_NB];
__device__ int   g_boff[SCAN_NB];
__device__ __half g_gbuf[(size_t)NN * DH];     // fp16 messages (gather traffic /2)
__device__ float g_hag[(size_t)NN * DH];
__device__ float g_sum[NL * DH];
__device__ float g_sq[NL * DH];
__device__ float g_scale[NL * DH];
__device__ float g_shift[NL * DH];
__device__ int   g_cnt[NG];
// W^T bf16 hi/lo; per layer two 16KB slabs (k-halves), swizzled within slab
__device__ unsigned short g_whi[NL * 16384];
__device__ unsigned short g_wlo[NL * 16384];

__device__ __forceinline__ float elu1(float v) {
    return v > 0.f ? v : (expf(v) - 1.f);
}

// swizzled byte offset within a 128row x 64k bf16 (16KB) slab
__device__ __forceinline__ int swz64(int r, int kchunk) {
    return r * 128 + ((kchunk ^ (r & 7)) << 4);
}

// ---------------- launch 1: init everything + W convert ----------------
__global__ void k_init_all(const float* __restrict__ Ws) {
    int i = blockIdx.x * 256 + threadIdx.x;
    if (i < NN) g_deg[i] = 0;
    if (i < NL * DH) { g_sum[i] = 0.f; g_sq[i] = 0.f; }
    if (i < NG) g_cnt[i] = 0;
    if (i < NL * 16384) {
        int l = i >> 14;
        int rem = i & 16383;
        int n = rem & 127;
        int k = rem >> 7;
        float w = Ws[(size_t)l * 16384 + k * 128 + n];
        __nv_bfloat16 hi = __float2bfloat16(w);
        float lof = w - __bfloat162float(hi);
        __nv_bfloat16 lo = __float2bfloat16(lof);
        int half = k >> 6;
        int lc = (k & 63) >> 3;
        int off = swz64(n, lc) + (k & 7) * 2;
        int a = l * 16384 + half * 8192 + (off >> 1);
        g_whi[a] = __bfloat16_as_ushort(hi);
        g_wlo[a] = __bfloat16_as_ushort(lo);
    }
}

// ---------------- launch 2: degree histogram + graph counts ----------------
__global__ void k_deg(const int* __restrict__ dst, const int* __restrict__ bidx) {
    int e = blockIdx.x * blockDim.x + threadIdx.x;
    if (e < NE) atomicAdd(&g_deg[dst[e]], 1);
    if (e < NN) atomicAdd(&g_cnt[bidx[e]], 1);
}

// ---------------- launch 3: dinv ----------------
__global__ void k_dinv() {
    int i = blockIdx.x * blockDim.x + threadIdx.x;
    if (i < NN) g_dinv[i] = rsqrtf((float)(g_deg[i] + 1));
}

// ---------------- scans ----------------
__global__ void __launch_bounds__(SCAN_T) k_bsum() {
    int i = blockIdx.x * SCAN_T + threadIdx.x;
    int v = (i < NN) ? g_deg[i] : 0;
    #pragma unroll
    for (int o = 16; o; o >>= 1) v += __shfl_down_sync(0xffffffffu, v, o);
    __shared__ int ws[SCAN_T / 32];
    if ((threadIdx.x & 31) == 0) ws[threadIdx.x >> 5] = v;
    __syncthreads();
    if (threadIdx.x < SCAN_T / 32) {
        int s = ws[threadIdx.x];
        #pragma unroll
        for (int o = SCAN_T / 64; o; o >>= 1) s += __shfl_down_sync(0xffu, s, o);
        if (threadIdx.x == 0) g_bsum[blockIdx.x] = s;
    }
}

__global__ void __launch_bounds__(256) k_bscan() {
    int tid = threadIdx.x;
    int lane = tid & 31, wid = tid >> 5;
    int v = (tid < SCAN_NB) ? g_bsum[tid] : 0;
    int incl = v;
    #pragma unroll
    for (int o = 1; o < 32; o <<= 1) {
        int t = __shfl_up_sync(0xffffffffu, incl, o);
        if (lane >= o) incl += t;
    }
    __shared__ int wtot[8];
    if (lane == 31) wtot[wid] = incl;
    __syncthreads();
    if (tid < 8) {
        int s = wtot[tid];
        int si = s;
        #pragma unroll
        for (int o = 1; o < 8; o <<= 1) {
            int t = __shfl_up_sync(0xffu, si, o);
            if (tid >= o) si += t;
        }
        wtot[tid] = si - s;
    }
    __syncthreads();
    incl += wtot[wid];
    if (tid < SCAN_NB) g_boff[tid] = incl - v;
    if (tid == 255) g_off[NN] = incl;
}

__global__ void __launch_bounds__(SCAN_T) k_lscan() {
    int tid = threadIdx.x;
    int lane = tid & 31, wid = tid >> 5;
    int i = blockIdx.x * SCAN_T + tid;
    int v = (i < NN) ? g_deg[i] : 0;
    int incl = v;
    #pragma unroll
    for (int o = 1; o < 32; o <<= 1) {
        int t = __shfl_up_sync(0xffffffffu, incl, o);
        if (lane >= o) incl += t;
    }
    __shared__ int wtot[SCAN_T / 32];
    if (lane == 31) wtot[wid] = incl;
    __syncthreads();
    if (tid < SCAN_T / 32) {
        int s = wtot[tid];
        int si = s;
        #pragma unroll
        for (int o = 1; o < SCAN_T / 32; o <<= 1) {
            int t = __shfl_up_sync(0xffu, si, o);
            if (tid >= o) si += t;
        }
        wtot[tid] = si - s;
    }
    __syncthreads();
    int excl = incl - v + wtot[wid] + g_boff[blockIdx.x];
    if (i < NN) {
        g_off[i] = excl;
        g_cur[i] = excl;
    }
}

__global__ void k_fill(const int* __restrict__ src, const int* __restrict__ dst) {
    int e = blockIdx.x * blockDim.x + threadIdx.x;
    if (e < NE) {
        int d = dst[e];
        int pos = atomicAdd(&g_cur[d], 1);
        g_csr[pos] = src[e];
    }
}

// ---------------- HMMA GEMM: g = dinv * (A' @ W), output fp16 ----------------
// 128x128 block, K staged in two 64-wide halves through 64KB smem -> 2 CTA/SM.
#define SA_HI 0
#define SA_LO 16384
#define SB_HI 32768
#define SB_LO 49152
#define SM_TOTAL 65536

__device__ __forceinline__ void ldsm4(uint32_t& r0, uint32_t& r1, uint32_t& r2,
                                      uint32_t& r3, uint32_t addr) {
    asm volatile("ldmatrix.sync.aligned.m8n8.x4.shared.b16 {%0,%1,%2,%3}, [%4];"
                 : "=r"(r0), "=r"(r1), "=r"(r2), "=r"(r3) : "r"(addr));
}
__device__ __forceinline__ void mma16816(float* d, const uint32_t* a, const uint32_t* b) {
    asm volatile(
        "mma.sync.aligned.m16n8k16.row.col.f32.bf16.bf16.f32 "
        "{%0,%1,%2,%3}, {%4,%5,%6,%7}, {%8,%9}, {%0,%1,%2,%3};"
        : "+f"(d[0]), "+f"(d[1]), "+f"(d[2]), "+f"(d[3])
        : "r"(a[0]), "r"(a[1]), "r"(a[2]), "r"(a[3]), "r"(b[0]), "r"(b[1]));
}
#define CP_ASYNC16(dst, src) \
    asm volatile("cp.async.cg.shared.global [%0], [%1], 16;" :: "r"(dst), "l"(src))
#define CP_COMMIT() asm volatile("cp.async.commit_group;" ::: "memory")
#define CP_WAIT0() asm volatile("cp.async.wait_group 0;" ::: "memory")

__global__ void __launch_bounds__(256, 2) k_gemm_tc(int layer, const float* __restrict__ x) {
    extern __shared__ char sm[];
    uint32_t sm_u = smem_to_u32(sm);
    int tid = threadIdx.x;
    int wid = tid >> 5, lane = tid & 31;

    const float* A = (layer == 0) ? x : g_hag;
    const float* sc = g_scale + (layer > 0 ? (layer - 1) * DH : 0);
    const float* sh = g_shift + (layer > 0 ? (layer - 1) * DH : 0);

    int warp_m = (wid & 3) * 32;
    int warp_n = (wid >> 2) * 64;

    float acc[2][8][4];
    #pragma unroll
    for (int i = 0; i < 2; ++i)
        #pragma unroll
        for (int j = 0; j < 8; ++j)
            #pragma unroll
            for (int c = 0; c < 4; ++c) acc[i][j][c] = 0.f;

    int sub = lane >> 3, l7 = lane & 7;
    int a_r0 = warp_m + (sub & 1) * 8 + l7;
    int a_cadd = sub >> 1;
    int b_nsel = (sub >> 1) * 8 + l7;
    int b_cadd = sub & 1;

    int row = tid >> 1, hq = tid & 1;
    int gr = blockIdx.x * 128 + row;

    #pragma unroll
    for (int half = 0; half < 2; ++half) {
        {
            const char* wh = (const char*)(g_whi + layer * 16384 + half * 8192) + tid * 16;
            const char* wl = (const char*)(g_wlo + layer * 16384 + half * 8192) + tid * 16;
            uint32_t bh = sm_u + SB_HI + tid * 16;
            uint32_t bl = sm_u + SB_LO + tid * 16;
            #pragma unroll
            for (int i = 0; i < 4; ++i) {
                CP_ASYNC16(bh + i * 4096, wh + i * 4096);
                CP_ASYNC16(bl + i * 4096, wl + i * 4096);
            }
            CP_COMMIT();
        }
        if (gr < NN) {
            const float4* ap = (const float4*)(A + (size_t)gr * DH + half * 64 + hq * 32);
            #pragma unroll
            for (int c8 = 0; c8 < 4; ++c8) {
                int lc = hq * 4 + c8;
                float4 v0 = ap[c8 * 2];
                float4 v1 = ap[c8 * 2 + 1];
                float f[8] = {v0.x, v0.y, v0.z, v0.w, v1.x, v1.y, v1.z, v1.w};
                if (layer > 0) {
                    int k0 = half * 64 + lc * 8;
                    #pragma unroll
                    for (int c = 0; c < 8; ++c)
                        f[c] = elu1(fmaf(f[c], sc[k0 + c], sh[k0 + c]));
                }
                uint32_t hp[4], lp[4];
                #pragma unroll
                for (int p = 0; p < 4; ++p) {
                    __nv_bfloat16 h0 = __float2bfloat16(f[p * 2]);
                    __nv_bfloat16 h1 = __float2bfloat16(f[p * 2 + 1]);
                    __nv_bfloat16 l0 = __float2bfloat16(f[p * 2] - __bfloat162float(h0));
                    __nv_bfloat16 l1 = __float2bfloat16(f[p * 2 + 1] - __bfloat162float(h1));
                    hp[p] = (uint32_t)__bfloat16_as_ushort(h0) |
                            ((uint32_t)__bfloat16_as_ushort(h1) << 16);
                    lp[p] = (uint32_t)__bfloat16_as_ushort(l0) |
                            ((uint32_t)__bfloat16_as_ushort(l1) << 16);
                }
                int off = swz64(row, lc);
                *(int4*)(sm + SA_HI + off) = make_int4(hp[0], hp[1], hp[2], hp[3]);
                *(int4*)(sm + SA_LO + off) = make_int4(lp[0], lp[1], lp[2], lp[3]);
            }
        } else {
            int4 z = make_int4(0, 0, 0, 0);
            #pragma unroll
            for (int c8 = 0; c8 < 4; ++c8) {
                int off = swz64(row, hq * 4 + c8);
                *(int4*)(sm + SA_HI + off) = z;
                *(int4*)(sm + SA_LO + off) = z;
            }
        }
        CP_WAIT0();
        __syncthreads();

        uint32_t aHi = sm_u + SA_HI, aLo = sm_u + SA_LO;
        uint32_t bHi = sm_u + SB_HI, bLo = sm_u + SB_LO;
        #pragma unroll
        for (int ks = 0; ks < 4; ++ks) {
            int a_kc = ks * 2 + a_cadd;
            int b_kc = ks * 2 + b_cadd;

            uint32_t ah[2][4];
            #pragma unroll
            for (int mf = 0; mf < 2; ++mf)
                ldsm4(ah[mf][0], ah[mf][1], ah[mf][2], ah[mf][3],
                      aHi + swz64(a_r0 + mf * 16, a_kc));

            uint32_t bh[8][2];
            #pragma unroll
            for (int p = 0; p < 4; ++p)
                ldsm4(bh[p * 2][0], bh[p * 2][1], bh[p * 2 + 1][0], bh[p * 2 + 1][1],
                      bHi + swz64(warp_n + p * 16 + b_nsel, b_kc));

            #pragma unroll
            for (int mf = 0; mf < 2; ++mf)
                #pragma unroll
                for (int nf = 0; nf < 8; ++nf)
                    mma16816(acc[mf][nf], ah[mf], bh[nf]);

            uint32_t bl[8][2];
            #pragma unroll
            for (int p = 0; p < 4; ++p)
                ldsm4(bl[p * 2][0], bl[p * 2][1], bl[p * 2 + 1][0], bl[p * 2 + 1][1],
                      bLo + swz64(warp_n + p * 16 + b_nsel, b_kc));

            #pragma unroll
            for (int mf = 0; mf < 2; ++mf)
                #pragma unroll
                for (int nf = 0; nf < 8; ++nf)
                    mma16816(acc[mf][nf], ah[mf], bl[nf]);

            uint32_t al[2][4];
            #pragma unroll
            for (int mf = 0; mf < 2; ++mf)
                ldsm4(al[mf][0], al[mf][1], al[mf][2], al[mf][3],
                      aLo + swz64(a_r0 + mf * 16, a_kc));

            #pragma unroll
            for (int mf = 0; mf < 2; ++mf)
                #pragma unroll
                for (int nf = 0; nf < 8; ++nf)
                    mma16816(acc[mf][nf], al[mf], bh[nf]);
        }
        if (half == 0) __syncthreads();
    }

    // --- epilogue: scale by dinv, convert fp16, store
    int qr = lane >> 2, qc = (lane & 3) * 2;
    #pragma unroll
    for (int mf = 0; mf < 2; ++mf) {
        int r0 = blockIdx.x * 128 + warp_m + mf * 16 + qr;
        int r1 = r0 + 8;
        float d0 = (r0 < NN) ? g_dinv[r0] : 0.f;
        float d1 = (r1 < NN) ? g_dinv[r1] : 0.f;
        #pragma unroll
        for (int nf = 0; nf < 8; ++nf) {
            int col = warp_n + nf * 8 + qc;
            if (r0 < NN) {
                __half2 o = __floats2half2_rn(acc[mf][nf][0] * d0, acc[mf][nf][1] * d0);
                *(__half2*)(g_gbuf + (size_t)r0 * DH + col) = o;
            }
            if (r1 < NN) {
                __half2 o = __floats2half2_rn(acc[mf][nf][2] * d1, acc[mf][nf][3] * d1);
                *(__half2*)(g_gbuf + (size_t)r1 * DH + col) = o;
            }
        }
    }
}

// ---------------- aggregation: fp16 gather, fp32 accumulate ----------
__device__ __forceinline__ void add_h4(float4& a, uint2 u) {
    float2 p0 = __half22float2(*(__half2*)&u.x);
    float2 p1 = __half22float2(*(__half2*)&u.y);
    a.x += p0.x; a.y += p0.y; a.z += p1.x; a.w += p1.y;
}

__global__ void __launch_bounds__(256) k_agg(int layer, const float* __restrict__ bias) {
    __shared__ float s_sum[DH];
    __shared__ float s_sq[DH];
    int tid = threadIdx.x;
    if (tid < DH) { s_sum[tid] = 0.f; s_sq[tid] = 0.f; }
    __syncthreads();

    int warp = tid >> 5, lane = tid & 31;
    int base = blockIdx.x * 32 + warp * 4;
    int f = lane * 4;
    float4 b = ((const float4*)bias)[lane];

    float ls0 = 0.f, ls1 = 0.f, ls2 = 0.f, ls3 = 0.f;
    float lq0 = 0.f, lq1 = 0.f, lq2 = 0.f, lq3 = 0.f;

    int nend = base + 4 < NN ? base + 4 : NN;
    for (int node = base; node < nend; ++node) {
        float4 a0 = make_float4(0.f, 0.f, 0.f, 0.f);
        float4 a1 = make_float4(0.f, 0.f, 0.f, 0.f);
        add_h4(a0, *(const uint2*)(g_gbuf + (size_t)node * DH + f));   // self
        int s = g_off[node], e2 = g_off[node + 1];
        int p = s;
        for (; p + 3 < e2; p += 4) {
            int s0 = g_csr[p], s1 = g_csr[p + 1], s2 = g_csr[p + 2], s3 = g_csr[p + 3];
            uint2 u0 = *(const uint2*)(g_gbuf + (size_t)s0 * DH + f);
            uint2 u1 = *(const uint2*)(g_gbuf + (size_t)s1 * DH + f);
            uint2 u2 = *(const uint2*)(g_gbuf + (size_t)s2 * DH + f);
            uint2 u3 = *(const uint2*)(g_gbuf + (size_t)s3 * DH + f);
            add_h4(a0, u0); add_h4(a1, u1); add_h4(a0, u2); add_h4(a1, u3);
        }
        for (; p < e2; ++p) {
            int s0 = g_csr[p];
            add_h4(a0, *(const uint2*)(g_gbuf + (size_t)s0 * DH + f));
        }
        float di = g_dinv[node];
        float4 h;
        h.x = fmaf(di, a0.x + a1.x, b.x);
        h.y = fmaf(di, a0.y + a1.y, b.y);
        h.z = fmaf(di, a0.z + a1.z, b.z);
        h.w = fmaf(di, a0.w + a1.w, b.w);
        *(float4*)(g_hag + (size_t)node * DH + f) = h;

        ls0 += h.x; lq0 += h.x * h.x;
        ls1 += h.y; lq1 += h.y * h.y;
        ls2 += h.z; lq2 += h.z * h.z;
        ls3 += h.w; lq3 += h.w * h.w;
    }
    atomicAdd(&s_sum[f + 0], ls0); atomicAdd(&s_sq[f + 0], lq0);
    atomicAdd(&s_sum[f + 1], ls1); atomicAdd(&s_sq[f + 1], lq1);
    atomicAdd(&s_sum[f + 2], ls2); atomicAdd(&s_sq[f + 2], lq2);
    atomicAdd(&s_sum[f + 3], ls3); atomicAdd(&s_sq[f + 3], lq3);
    __syncthreads();
    if (tid < DH) {
        atomicAdd(&g_sum[layer * DH + tid], s_sum[tid]);
        atomicAdd(&g_sq[layer * DH + tid], s_sq[tid]);
    }
}

// ---------------- BN finalize ----------------
__global__ void k_fin(int layer, const float* __restrict__ gamma,
                      const float* __restrict__ beta) {
    int h = threadIdx.x;
    float m = g_sum[layer * DH + h] * (1.f / NN);
    float var = g_sq[layer * DH + h] * (1.f / NN) - m * m;
    float rs = rsqrtf(var + BN_EPS);
    float sc = gamma[h] * rs;
    g_scale[layer * DH + h] = sc;
    g_shift[layer * DH + h] = beta[h] - m * sc;
}

// ---------------- pooling ----------------
__global__ void __launch_bounds__(256) k_pool(const int* __restrict__ bidx,
                                              float* __restrict__ out) {
    int tid = threadIdx.x;
    int warp = (blockIdx.x * 8 + (tid >> 5));
    int base = warp * 8;
    if (base >= NN) return;
    int lane = tid & 31;
    int f = lane * 4;
    const int L2 = (NL - 1) * DH;
    float s0 = g_scale[L2 + f], s1 = g_scale[L2 + f + 1],
          s2 = g_scale[L2 + f + 2], s3 = g_scale[L2 + f + 3];
    float t0 = g_shift[L2 + f], t1 = g_shift[L2 + f + 1],
          t2 = g_shift[L2 + f + 2], t3 = g_shift[L2 + f + 3];

    float a0 = 0.f, a1 = 0.f, a2 = 0.f, a3 = 0.f;
    int cur = bidx[base];
    int end = base + 8 < NN ? base + 8 : NN;
    for (int n = base; n < end; ++n) {
        int gi = bidx[n];
        if (gi != cur) {
            float* o = out + (size_t)cur * DH + f;
            atomicAdd(o + 0, a0); atomicAdd(o + 1, a1);
            atomicAdd(o + 2, a2); atomicAdd(o + 3, a3);
            a0 = a1 = a2 = a3 = 0.f;
            cur = gi;
        }
        float4 h = *(const float4*)(g_hag + (size_t)n * DH + f);
        a0 += elu1(fmaf(h.x, s0, t0));
        a1 += elu1(fmaf(h.y, s1, t1));
        a2 += elu1(fmaf(h.z, s2, t2));
        a3 += elu1(fmaf(h.w, s3, t3));
    }
    float* o = out + (size_t)cur * DH + f;
    atomicAdd(o + 0, a0); atomicAdd(o + 1, a1);
    atomicAdd(o + 2, a2); atomicAdd(o + 3, a3);
}

__global__ void k_div(float* __restrict__ out) {
    int i = blockIdx.x * blockDim.x + threadIdx.x;
    if (i < NG * DH) {
        float c = (float)g_cnt[i >> 7];
        out[i] = out[i] / fmaxf(c, 1.f);
    }
}

// ---------------- launch ----------------
extern "C" void kernel_launch(void* const* d_in, const int* in_sizes, int n_in,
                              void* d_out, int out_size) {
    const float* x      = (const float*)d_in[0];
    const float* Ws     = (const float*)d_in[1];
    const float* bs     = (const float*)d_in[2];
    const float* gammas = (const float*)d_in[3];
    const float* betas  = (const float*)d_in[4];
    const int*   ei     = (const int*)d_in[5];
    const int*   bidx   = (const int*)d_in[6];
    float*       out    = (float*)d_out;

    const int* src = ei;
    const int* dst = ei + NE;

    cudaFuncSetAttribute(k_gemm_tc, cudaFuncAttributeMaxDynamicSharedMemorySize, SM_TOTAL);

    int gemm_grid = (NN + 127) / 128;
    int agg_grid = (NN + 31) / 32;

    k_init_all<<<(NN + 255) / 256, 256>>>(Ws);          // 1
    k_deg<<<(NE + 255) / 256, 256>>>(dst, bidx);        // 2
    k_dinv<<<(NN + 255) / 256, 256>>>();                // 3
    k_gemm_tc<<<gemm_grid, 256, SM_TOTAL>>>(0, x);      // 4  <- ncu capture slot
    k_bsum<<<SCAN_NB, SCAN_T>>>();                      // 5
    k_bscan<<<1, 256>>>();                              // 6
    k_lscan<<<SCAN_NB, SCAN_T>>>();                     // 7
    k_fill<<<(NE + 255) / 256, 256>>>(src, dst);        // 8

    k_agg<<<agg_grid, 256>>>(0, bs);                    // 9
    k_fin<<<1, DH>>>(0, gammas, betas);
    for (int l = 1; l < NL; ++l) {
        k_gemm_tc<<<gemm_grid, 256, SM_TOTAL>>>(l, x);
        k_agg<<<agg_grid, 256>>>(l, bs + l * DH);
        k_fin<<<1, DH>>>(l, gammas + l * DH, betas + l * DH);
    }

    cudaMemsetAsync(d_out, 0, (size_t)NG * DH * sizeof(float));
    int pool_grid = (NN + 63) / 64;
    k_pool<<<pool_grid, 256>>>(bidx, out);
    k_div<<<(NG * DH + 255) / 256, 256>>>(out);
}

// round 10
// speedup vs baseline: 1.5065x; 1.1424x over previous
#include <cuda_runtime.h>
#include <cuda_fp16.h>
#include <math.h>
#include <stdint.h>

#define NN 50000
#define NE 640000
#define DH 128
#define NG 1024
#define NL 3
#define BN_EPS 1e-5f

#define SCAN_T 256
#define SCAN_NB ((NN + SCAN_T - 1) / SCAN_T)   // 196

__device__ __forceinline__ uint32_t smem_to_u32(const void* p) {
    uint32_t a;
    asm("{ .reg .u64 t; cvta.to.shared.u64 t, %1; cvt.u32.u64 %0, t; }" : "=r"(a) : "l"(p));
    return a;
}

// ---------------- scratch ----------------
__device__ int   g_deg[NN];
__device__ int   g_off[NN + 1];
__device__ int   g_cur[NN];
__device__ float g_dinv[NN];
__device__ int   g_csr[NE];
__device__ int   g_bsum[SCAN_NB];
__device__ int   g_boff[SCAN_NB];
__device__ __half g_gbuf[(size_t)NN * DH];     // fp16 messages
__device__ __half g_hag[(size_t)NN * DH];      // fp16 aggregated h
__device__ float g_sum[NL * DH];
__device__ float g_sq[NL * DH];
__device__ float g_scale[NL * DH];
__device__ float g_shift[NL * DH];
__device__ int   g_cnt[NG];
// W^T fp16 hi/lo; per layer two 16KB slabs (k-halves), swizzled within slab
__device__ unsigned short g_whi[NL * 16384];
__device__ unsigned short g_wlo[NL * 16384];

__device__ __forceinline__ float elu1(float v) {
    return v > 0.f ? v : (expf(v) - 1.f);
}

// swizzled byte offset within a 128row x 64k fp16 (16KB) slab
__device__ __forceinline__ int swz64(int r, int kchunk) {
    return r * 128 + ((kchunk ^ (r & 7)) << 4);
}

// ---------------- launch 1: init everything + W convert ----------------
__global__ void k_init_all(const float* __restrict__ Ws) {
    int i = blockIdx.x * 256 + threadIdx.x;
    if (i < NN) g_deg[i] = 0;
    if (i < NL * DH) { g_sum[i] = 0.f; g_sq[i] = 0.f; }
    if (i < NG) g_cnt[i] = 0;
    if (i < NL * 16384) {
        int l = i >> 14;
        int rem = i & 16383;
        int n = rem & 127;
        int k = rem >> 7;
        float w = Ws[(size_t)l * 16384 + k * 128 + n];
        __half hi = __float2half_rn(w);
        __half lo = __float2half_rn(w - __half2float(hi));
        int half = k >> 6;
        int lc = (k & 63) >> 3;
        int off = swz64(n, lc) + (k & 7) * 2;
        int a = l * 16384 + half * 8192 + (off >> 1);
        g_whi[a] = __half_as_ushort(hi);
        g_wlo[a] = __half_as_ushort(lo);
    }
}

// ---------------- launch 2: degree histogram + graph counts ----------------
__global__ void k_deg(const int* __restrict__ dst, const int* __restrict__ bidx) {
    int e = blockIdx.x * blockDim.x + threadIdx.x;
    if (e < NE) atomicAdd(&g_deg[dst[e]], 1);
    if (e < NN) atomicAdd(&g_cnt[bidx[e]], 1);
}

// ---------------- launch 3: dinv ----------------
__global__ void k_dinv() {
    int i = blockIdx.x * blockDim.x + threadIdx.x;
    if (i < NN) g_dinv[i] = rsqrtf((float)(g_deg[i] + 1));
}

// ---------------- scans ----------------
__global__ void __launch_bounds__(SCAN_T) k_bsum() {
    int i = blockIdx.x * SCAN_T + threadIdx.x;
    int v = (i < NN) ? g_deg[i] : 0;
    #pragma unroll
    for (int o = 16; o; o >>= 1) v += __shfl_down_sync(0xffffffffu, v, o);
    __shared__ int ws[SCAN_T / 32];
    if ((threadIdx.x & 31) == 0) ws[threadIdx.x >> 5] = v;
    __syncthreads();
    if (threadIdx.x < SCAN_T / 32) {
        int s = ws[threadIdx.x];
        #pragma unroll
        for (int o = SCAN_T / 64; o; o >>= 1) s += __shfl_down_sync(0xffu, s, o);
        if (threadIdx.x == 0) g_bsum[blockIdx.x] = s;
    }
}

__global__ void __launch_bounds__(256) k_bscan() {
    int tid = threadIdx.x;
    int lane = tid & 31, wid = tid >> 5;
    int v = (tid < SCAN_NB) ? g_bsum[tid] : 0;
    int incl = v;
    #pragma unroll
    for (int o = 1; o < 32; o <<= 1) {
        int t = __shfl_up_sync(0xffffffffu, incl, o);
        if (lane >= o) incl += t;
    }
    __shared__ int wtot[8];
    if (lane == 31) wtot[wid] = incl;
    __syncthreads();
    if (tid < 8) {
        int s = wtot[tid];
        int si = s;
        #pragma unroll
        for (int o = 1; o < 8; o <<= 1) {
            int t = __shfl_up_sync(0xffu, si, o);
            if (tid >= o) si += t;
        }
        wtot[tid] = si - s;
    }
    __syncthreads();
    incl += wtot[wid];
    if (tid < SCAN_NB) g_boff[tid] = incl - v;
    if (tid == 255) g_off[NN] = incl;
}

__global__ void __launch_bounds__(SCAN_T) k_lscan() {
    int tid = threadIdx.x;
    int lane = tid & 31, wid = tid >> 5;
    int i = blockIdx.x * SCAN_T + tid;
    int v = (i < NN) ? g_deg[i] : 0;
    int incl = v;
    #pragma unroll
    for (int o = 1; o < 32; o <<= 1) {
        int t = __shfl_up_sync(0xffffffffu, incl, o);
        if (lane >= o) incl += t;
    }
    __shared__ int wtot[SCAN_T / 32];
    if (lane == 31) wtot[wid] = incl;
    __syncthreads();
    if (tid < SCAN_T / 32) {
        int s = wtot[tid];
        int si = s;
        #pragma unroll
        for (int o = 1; o < SCAN_T / 32; o <<= 1) {
            int t = __shfl_up_sync(0xffu, si, o);
            if (tid >= o) si += t;
        }
        wtot[tid] = si - s;
    }
    __syncthreads();
    int excl = incl - v + wtot[wid] + g_boff[blockIdx.x];
    if (i < NN) {
        g_off[i] = excl;
        g_cur[i] = excl;
    }
}

__global__ void k_fill(const int* __restrict__ src, const int* __restrict__ dst) {
    int e = blockIdx.x * blockDim.x + threadIdx.x;
    if (e < NE) {
        int d = dst[e];
        int pos = atomicAdd(&g_cur[d], 1);
        g_csr[pos] = src[e];
    }
}

// ---------------- HMMA GEMM: g = dinv * (A' @ W), fp16 A single, W hi/lo ----
// 128x128 block, K staged in two 64-wide halves through 48KB smem, 2 CTA/SM.
#define SA    0
#define SB_HI 16384
#define SB_LO 32768
#define SM_TOTAL 49152

__device__ __forceinline__ void ldsm4(uint32_t& r0, uint32_t& r1, uint32_t& r2,
                                      uint32_t& r3, uint32_t addr) {
    asm volatile("ldmatrix.sync.aligned.m8n8.x4.shared.b16 {%0,%1,%2,%3}, [%4];"
                 : "=r"(r0), "=r"(r1), "=r"(r2), "=r"(r3) : "r"(addr));
}
__device__ __forceinline__ void mma16816(float* d, const uint32_t* a, const uint32_t* b) {
    asm volatile(
        "mma.sync.aligned.m16n8k16.row.col.f32.f16.f16.f32 "
        "{%0,%1,%2,%3}, {%4,%5,%6,%7}, {%8,%9}, {%0,%1,%2,%3};"
        : "+f"(d[0]), "+f"(d[1]), "+f"(d[2]), "+f"(d[3])
        : "r"(a[0]), "r"(a[1]), "r"(a[2]), "r"(a[3]), "r"(b[0]), "r"(b[1]));
}
#define CP_ASYNC16(dst, src) \
    asm volatile("cp.async.cg.shared.global [%0], [%1], 16;" :: "r"(dst), "l"(src))
#define CP_COMMIT() asm volatile("cp.async.commit_group;" ::: "memory")
#define CP_WAIT0() asm volatile("cp.async.wait_group 0;" ::: "memory")

__global__ void __launch_bounds__(256, 2) k_gemm_tc(int layer, const float* __restrict__ x) {
    extern __shared__ char sm[];
    uint32_t sm_u = smem_to_u32(sm);
    int tid = threadIdx.x;
    int wid = tid >> 5, lane = tid & 31;

    const float* sc = g_scale + (layer > 0 ? (layer - 1) * DH : 0);
    const float* sh = g_shift + (layer > 0 ? (layer - 1) * DH : 0);

    int warp_m = (wid & 3) * 32;
    int warp_n = (wid >> 2) * 64;

    float acc[2][8][4];
    #pragma unroll
    for (int i = 0; i < 2; ++i)
        #pragma unroll
        for (int j = 0; j < 8; ++j)
            #pragma unroll
            for (int c = 0; c < 4; ++c) acc[i][j][c] = 0.f;

    int sub = lane >> 3, l7 = lane & 7;
    int a_r0 = warp_m + (sub & 1) * 8 + l7;
    int a_cadd = sub >> 1;
    int b_nsel = (sub >> 1) * 8 + l7;
    int b_cadd = sub & 1;

    int row = tid >> 1, hq = tid & 1;
    int gr = blockIdx.x * 128 + row;

    #pragma unroll
    for (int half = 0; half < 2; ++half) {
        {
            const char* wh = (const char*)(g_whi + layer * 16384 + half * 8192) + tid * 16;
            const char* wl = (const char*)(g_wlo + layer * 16384 + half * 8192) + tid * 16;
            uint32_t bh = sm_u + SB_HI + tid * 16;
            uint32_t bl = sm_u + SB_LO + tid * 16;
            #pragma unroll
            for (int i = 0; i < 4; ++i) {
                CP_ASYNC16(bh + i * 4096, wh + i * 4096);
                CP_ASYNC16(bl + i * 4096, wl + i * 4096);
            }
            CP_COMMIT();
        }
        // --- convert A' (32 values per thread) for this k-half, fp16 single
        if (gr < NN) {
            #pragma unroll
            for (int c8 = 0; c8 < 4; ++c8) {
                int lc = hq * 4 + c8;            // local kchunk 0..7
                int k0 = half * 64 + lc * 8;     // global k of first elem
                float f[8];
                if (layer == 0) {
                    float4 v0 = *(const float4*)(x + (size_t)gr * DH + k0);
                    float4 v1 = *(const float4*)(x + (size_t)gr * DH + k0 + 4);
                    f[0] = v0.x; f[1] = v0.y; f[2] = v0.z; f[3] = v0.w;
                    f[4] = v1.x; f[5] = v1.y; f[6] = v1.z; f[7] = v1.w;
                } else {
                    int4 u = *(const int4*)(g_hag + (size_t)gr * DH + k0);
                    float2 p0 = __half22float2(*(__half2*)&u.x);
                    float2 p1 = __half22float2(*(__half2*)&u.y);
                    float2 p2 = __half22float2(*(__half2*)&u.z);
                    float2 p3 = __half22float2(*(__half2*)&u.w);
                    f[0] = p0.x; f[1] = p0.y; f[2] = p1.x; f[3] = p1.y;
                    f[4] = p2.x; f[5] = p2.y; f[6] = p3.x; f[7] = p3.y;
                    #pragma unroll
                    for (int c = 0; c < 8; ++c)
                        f[c] = elu1(fmaf(f[c], sc[k0 + c], sh[k0 + c]));
                }
                uint32_t hp[4];
                #pragma unroll
                for (int p = 0; p < 4; ++p) {
                    __half2 h2 = __floats2half2_rn(f[p * 2], f[p * 2 + 1]);
                    hp[p] = *(uint32_t*)&h2;
                }
                *(int4*)(sm + SA + swz64(row, lc)) = make_int4(hp[0], hp[1], hp[2], hp[3]);
            }
        } else {
            int4 z = make_int4(0, 0, 0, 0);
            #pragma unroll
            for (int c8 = 0; c8 < 4; ++c8)
                *(int4*)(sm + SA + swz64(row, hq * 4 + c8)) = z;
        }
        CP_WAIT0();
        __syncthreads();

        // --- mainloop for this half: 4 k-steps, 2-pass (W hi + W lo)
        uint32_t aB = sm_u + SA;
        uint32_t bHi = sm_u + SB_HI, bLo = sm_u + SB_LO;
        #pragma unroll
        for (int ks = 0; ks < 4; ++ks) {
            int a_kc = ks * 2 + a_cadd;
            int b_kc = ks * 2 + b_cadd;

            uint32_t a[2][4];
            #pragma unroll
            for (int mf = 0; mf < 2; ++mf)
                ldsm4(a[mf][0], a[mf][1], a[mf][2], a[mf][3],
                      aB + swz64(a_r0 + mf * 16, a_kc));

            uint32_t bh[8][2];
            #pragma unroll
            for (int p = 0; p < 4; ++p)
                ldsm4(bh[p * 2][0], bh[p * 2][1], bh[p * 2 + 1][0], bh[p * 2 + 1][1],
                      bHi + swz64(warp_n + p * 16 + b_nsel, b_kc));

            #pragma unroll
            for (int mf = 0; mf < 2; ++mf)
                #pragma unroll
                for (int nf = 0; nf < 8; ++nf)
                    mma16816(acc[mf][nf], a[mf], bh[nf]);

            uint32_t bl[8][2];
            #pragma unroll
            for (int p = 0; p < 4; ++p)
                ldsm4(bl[p * 2][0], bl[p * 2][1], bl[p * 2 + 1][0], bl[p * 2 + 1][1],
                      bLo + swz64(warp_n + p * 16 + b_nsel, b_kc));

            #pragma unroll
            for (int mf = 0; mf < 2; ++mf)
                #pragma unroll
                for (int nf = 0; nf < 8; ++nf)
                    mma16816(acc[mf][nf], a[mf], bl[nf]);
        }
        if (half == 0) __syncthreads();
    }

    // --- epilogue: scale by dinv, convert fp16, store
    int qr = lane >> 2, qc = (lane & 3) * 2;
    #pragma unroll
    for (int mf = 0; mf < 2; ++mf) {
        int r0 = blockIdx.x * 128 + warp_m + mf * 16 + qr;
        int r1 = r0 + 8;
        float d0 = (r0 < NN) ? g_dinv[r0] : 0.f;
        float d1 = (r1 < NN) ? g_dinv[r1] : 0.f;
        #pragma unroll
        for (int nf = 0; nf < 8; ++nf) {
            int col = warp_n + nf * 8 + qc;
            if (r0 < NN) {
                __half2 o = __floats2half2_rn(acc[mf][nf][0] * d0, acc[mf][nf][1] * d0);
                *(__half2*)(g_gbuf + (size_t)r0 * DH + col) = o;
            }
            if (r1 < NN) {
                __half2 o = __floats2half2_rn(acc[mf][nf][2] * d1, acc[mf][nf][3] * d1);
                *(__half2*)(g_gbuf + (size_t)r1 * DH + col) = o;
            }
        }
    }
}

// ---------------- aggregation: fp16 gather, fp32 accumulate, fp16 h ----------
__device__ __forceinline__ void add_h4(float4& a, uint2 u) {
    float2 p0 = __half22float2(*(__half2*)&u.x);
    float2 p1 = __half22float2(*(__half2*)&u.y);
    a.x += p0.x; a.y += p0.y; a.z += p1.x; a.w += p1.y;
}

__global__ void __launch_bounds__(256) k_agg(int layer, const float* __restrict__ bias) {
    __shared__ float s_sum[DH];
    __shared__ float s_sq[DH];
    int tid = threadIdx.x;
    if (tid < DH) { s_sum[tid] = 0.f; s_sq[tid] = 0.f; }
    __syncthreads();

    int warp = tid >> 5, lane = tid & 31;
    int base = blockIdx.x * 32 + warp * 4;
    int f = lane * 4;
    float4 b = ((const float4*)bias)[lane];

    float ls0 = 0.f, ls1 = 0.f, ls2 = 0.f, ls3 = 0.f;
    float lq0 = 0.f, lq1 = 0.f, lq2 = 0.f, lq3 = 0.f;

    int nend = base + 4 < NN ? base + 4 : NN;
    for (int node = base; node < nend; ++node) {
        float4 a0 = make_float4(0.f, 0.f, 0.f, 0.f);
        float4 a1 = make_float4(0.f, 0.f, 0.f, 0.f);
        add_h4(a0, *(const uint2*)(g_gbuf + (size_t)node * DH + f));   // self
        int s = g_off[node], e2 = g_off[node + 1];
        int p = s;
        for (; p + 3 < e2; p += 4) {
            int s0 = g_csr[p], s1 = g_csr[p + 1], s2 = g_csr[p + 2], s3 = g_csr[p + 3];
            uint2 u0 = *(const uint2*)(g_gbuf + (size_t)s0 * DH + f);
            uint2 u1 = *(const uint2*)(g_gbuf + (size_t)s1 * DH + f);
            uint2 u2 = *(const uint2*)(g_gbuf + (size_t)s2 * DH + f);
            uint2 u3 = *(const uint2*)(g_gbuf + (size_t)s3 * DH + f);
            add_h4(a0, u0); add_h4(a1, u1); add_h4(a0, u2); add_h4(a1, u3);
        }
        for (; p < e2; ++p) {
            int s0 = g_csr[p];
            add_h4(a0, *(const uint2*)(g_gbuf + (size_t)s0 * DH + f));
        }
        float di = g_dinv[node];
        float4 h;
        h.x = fmaf(di, a0.x + a1.x, b.x);
        h.y = fmaf(di, a0.y + a1.y, b.y);
        h.z = fmaf(di, a0.z + a1.z, b.z);
        h.w = fmaf(di, a0.w + a1.w, b.w);
        __half2 o0 = __floats2half2_rn(h.x, h.y);
        __half2 o1 = __floats2half2_rn(h.z, h.w);
        uint2 ov;
        ov.x = *(uint32_t*)&o0;
        ov.y = *(uint32_t*)&o1;
        *(uint2*)(g_hag + (size_t)node * DH + f) = ov;

        ls0 += h.x; lq0 += h.x * h.x;
        ls1 += h.y; lq1 += h.y * h.y;
        ls2 += h.z; lq2 += h.z * h.z;
        ls3 += h.w; lq3 += h.w * h.w;
    }
    atomicAdd(&s_sum[f + 0], ls0); atomicAdd(&s_sq[f + 0], lq0);
    atomicAdd(&s_sum[f + 1], ls1); atomicAdd(&s_sq[f + 1], lq1);
    atomicAdd(&s_sum[f + 2], ls2); atomicAdd(&s_sq[f + 2], lq2);
    atomicAdd(&s_sum[f + 3], ls3); atomicAdd(&s_sq[f + 3], lq3);
    __syncthreads();
    if (tid < DH) {
        atomicAdd(&g_sum[layer * DH + tid], s_sum[tid]);
        atomicAdd(&g_sq[layer * DH + tid], s_sq[tid]);
    }
}

// ---------------- BN finalize ----------------
__global__ void k_fin(int layer, const float* __restrict__ gamma,
                      const float* __restrict__ beta) {
    int h = threadIdx.x;
    float m = g_sum[layer * DH + h] * (1.f / NN);
    float var = g_sq[layer * DH + h] * (1.f / NN) - m * m;
    float rs = rsqrtf(var + BN_EPS);
    float sc = gamma[h] * rs;
    g_scale[layer * DH + h] = sc;
    g_shift[layer * DH + h] = beta[h] - m * sc;
}

// ---------------- pooling (fp16 h reads) ----------------
__global__ void __launch_bounds__(256) k_pool(const int* __restrict__ bidx,
                                              float* __restrict__ out) {
    int tid = threadIdx.x;
    int warp = (blockIdx.x * 8 + (tid >> 5));
    int base = warp * 8;
    if (base >= NN) return;
    int lane = tid & 31;
    int f = lane * 4;
    const int L2 = (NL - 1) * DH;
    float s0 = g_scale[L2 + f], s1 = g_scale[L2 + f + 1],
          s2 = g_scale[L2 + f + 2], s3 = g_scale[L2 + f + 3];
    float t0 = g_shift[L2 + f], t1 = g_shift[L2 + f + 1],
          t2 = g_shift[L2 + f + 2], t3 = g_shift[L2 + f + 3];

    float a0 = 0.f, a1 = 0.f, a2 = 0.f, a3 = 0.f;
    int cur = bidx[base];
    int end = base + 8 < NN ? base + 8 : NN;
    for (int n = base; n < end; ++n) {
        int gi = bidx[n];
        if (gi != cur) {
            float* o = out + (size_t)cur * DH + f;
            atomicAdd(o + 0, a0); atomicAdd(o + 1, a1);
            atomicAdd(o + 2, a2); atomicAdd(o + 3, a3);
            a0 = a1 = a2 = a3 = 0.f;
            cur = gi;
        }
        uint2 u = *(const uint2*)(g_hag + (size_t)n * DH + f);
        float2 p0 = __half22float2(*(__half2*)&u.x);
        float2 p1 = __half22float2(*(__half2*)&u.y);
        a0 += elu1(fmaf(p0.x, s0, t0));
        a1 += elu1(fmaf(p0.y, s1, t1));
        a2 += elu1(fmaf(p1.x, s2, t2));
        a3 += elu1(fmaf(p1.y, s3, t3));
    }
    float* o = out + (size_t)cur * DH + f;
    atomicAdd(o + 0, a0); atomicAdd(o + 1, a1);
    atomicAdd(o + 2, a2); atomicAdd(o + 3, a3);
}

__global__ void k_div(float* __restrict__ out) {
    int i = blockIdx.x * blockDim.x + threadIdx.x;
    if (i < NG * DH) {
        float c = (float)g_cnt[i >> 7];
        out[i] = out[i] / fmaxf(c, 1.f);
    }
}

// ---------------- launch ----------------
extern "C" void kernel_launch(void* const* d_in, const int* in_sizes, int n_in,
                              void* d_out, int out_size) {
    const float* x      = (const float*)d_in[0];
    const float* Ws     = (const float*)d_in[1];
    const float* bs     = (const float*)d_in[2];
    const float* gammas = (const float*)d_in[3];
    const float* betas  = (const float*)d_in[4];
    const int*   ei     = (const int*)d_in[5];
    const int*   bidx   = (const int*)d_in[6];
    float*       out    = (float*)d_out;

    const int* src = ei;
    const int* dst = ei + NE;

    cudaFuncSetAttribute(k_gemm_tc, cudaFuncAttributeMaxDynamicSharedMemorySize, SM_TOTAL);

    int gemm_grid = (NN + 127) / 128;
    int agg_grid = (NN + 31) / 32;

    k_init_all<<<(NN + 255) / 256, 256>>>(Ws);          // 1
    k_deg<<<(NE + 255) / 256, 256>>>(dst, bidx);        // 2
    k_dinv<<<(NN + 255) / 256, 256>>>();                // 3
    k_gemm_tc<<<gemm_grid, 256, SM_TOTAL>>>(0, x);      // 4  <- ncu capture slot
    k_bsum<<<SCAN_NB, SCAN_T>>>();                      // 5
    k_bscan<<<1, 256>>>();                              // 6
    k_lscan<<<SCAN_NB, SCAN_T>>>();                     // 7
    k_fill<<<(NE + 255) / 256, 256>>>(src, dst);        // 8

    k_agg<<<agg_grid, 256>>>(0, bs);                    // 9
    k_fin<<<1, DH>>>(0, gammas, betas);
    for (int l = 1; l < NL; ++l) {
        k_gemm_tc<<<gemm_grid, 256, SM_TOTAL>>>(l, x);
        k_agg<<<agg_grid, 256>>>(l, bs + l * DH);
        k_fin<<<1, DH>>>(l, gammas + l * DH, betas + l * DH);
    }

    cudaMemsetAsync(d_out, 0, (size_t)NG * DH * sizeof(float));
    int pool_grid = (NN + 63) / 64;
    k_pool<<<pool_grid, 256>>>(bidx, out);
    k_div<<<(NG * DH + 255) / 256, 256>>>(out);
}

// round 11
// speedup vs baseline: 1.5608x; 1.0361x over previous
#include <cuda_runtime.h>
#include <cuda_fp16.h>
#include <math.h>
#include <stdint.h>

#define NN 50000
#define NE 640000
#define DH 128
#define NG 1024
#define NL 3
#define BN_EPS 1e-5f

#define SCAN_T 256
#define SCAN_NB ((NN + SCAN_T - 1) / SCAN_T)   // 196

__device__ __forceinline__ uint32_t smem_to_u32(const void* p) {
    uint32_t a;
    asm("{ .reg .u64 t; cvta.to.shared.u64 t, %1; cvt.u32.u64 %0, t; }" : "=r"(a) : "l"(p));
    return a;
}

// ---------------- scratch ----------------
__device__ int   g_deg[NN];
__device__ int   g_off[NN + 1];
__device__ int   g_cur[NN];
__device__ float g_dinv[NN];
__device__ int   g_csr[NE];
__device__ int   g_bsum[SCAN_NB];
__device__ __half g_gbuf[(size_t)NN * DH];     // fp16 messages
__device__ __half g_hag[(size_t)NN * DH];      // fp16 aggregated h
__device__ float g_sum[NL * DH];
__device__ float g_sq[NL * DH];
__device__ int   g_cnt[NG];
// W^T fp16 hi/lo; per layer two 16KB slabs (k-halves), swizzled within slab
__device__ unsigned short g_whi[NL * 16384];
__device__ unsigned short g_wlo[NL * 16384];

__device__ __forceinline__ float elu1(float v) {
    return v > 0.f ? v : (__expf(v) - 1.f);
}

// swizzled byte offset within a 128row x 64k fp16 (16KB) slab
__device__ __forceinline__ int swz64(int r, int kchunk) {
    return r * 128 + ((kchunk ^ (r & 7)) << 4);
}

// ---------------- launch 1: init everything + W convert ----------------
__global__ void k_init_all(const float* __restrict__ Ws) {
    int i = blockIdx.x * 256 + threadIdx.x;
    if (i < NN) g_deg[i] = 0;
    if (i < NL * DH) { g_sum[i] = 0.f; g_sq[i] = 0.f; }
    if (i < NG) g_cnt[i] = 0;
    if (i < NL * 16384) {
        int l = i >> 14;
        int rem = i & 16383;
        int n = rem & 127;
        int k = rem >> 7;
        float w = Ws[(size_t)l * 16384 + k * 128 + n];
        __half hi = __float2half_rn(w);
        __half lo = __float2half_rn(w - __half2float(hi));
        int half = k >> 6;
        int lc = (k & 63) >> 3;
        int off = swz64(n, lc) + (k & 7) * 2;
        int a = l * 16384 + half * 8192 + (off >> 1);
        g_whi[a] = __half_as_ushort(hi);
        g_wlo[a] = __half_as_ushort(lo);
    }
}

// ---------------- launch 2: degree histogram + graph counts ----------------
__global__ void k_deg(const int* __restrict__ dst, const int* __restrict__ bidx) {
    int e = blockIdx.x * blockDim.x + threadIdx.x;
    if (e < NE) atomicAdd(&g_deg[dst[e]], 1);
    if (e < NN) atomicAdd(&g_cnt[bidx[e]], 1);
}

// ---------------- launch 3: block sums + dinv ----------------
__global__ void __launch_bounds__(SCAN_T) k_bsum() {
    int i = blockIdx.x * SCAN_T + threadIdx.x;
    int v = (i < NN) ? g_deg[i] : 0;
    if (i < NN) g_dinv[i] = rsqrtf((float)(v + 1));   // +1 self loop
    #pragma unroll
    for (int o = 16; o; o >>= 1) v += __shfl_down_sync(0xffffffffu, v, o);
    __shared__ int ws[SCAN_T / 32];
    if ((threadIdx.x & 31) == 0) ws[threadIdx.x >> 5] = v;
    __syncthreads();
    if (threadIdx.x < SCAN_T / 32) {
        int s = ws[threadIdx.x];
        #pragma unroll
        for (int o = SCAN_T / 64; o; o >>= 1) s += __shfl_down_sync(0xffu, s, o);
        if (threadIdx.x == 0) g_bsum[blockIdx.x] = s;
    }
}

// ---------------- local scan with self-computed block offset ----------------
__global__ void __launch_bounds__(SCAN_T) k_lscan() {
    int tid = threadIdx.x;
    int lane = tid & 31, wid = tid >> 5;
    int bid = blockIdx.x;

    // block offset = sum of g_bsum[0..bid)  (SCAN_NB=196 < 256 threads)
    __shared__ int s_boff;
    __shared__ int wred[SCAN_T / 32];
    {
        int bv = (tid < bid) ? g_bsum[tid] : 0;
        #pragma unroll
        for (int o = 16; o; o >>= 1) bv += __shfl_down_sync(0xffffffffu, bv, o);
        if (lane == 0) wred[wid] = bv;
        __syncthreads();
        if (tid == 0) {
            int s = 0;
            #pragma unroll
            for (int w = 0; w < SCAN_T / 32; ++w) s += wred[w];
            s_boff = s;
        }
        __syncthreads();
    }

    int i = bid * SCAN_T + tid;
    int v = (i < NN) ? g_deg[i] : 0;
    int incl = v;
    #pragma unroll
    for (int o = 1; o < 32; o <<= 1) {
        int t = __shfl_up_sync(0xffffffffu, incl, o);
        if (lane >= o) incl += t;
    }
    __shared__ int wtot[SCAN_T / 32];
    if (lane == 31) wtot[wid] = incl;
    __syncthreads();
    if (tid < SCAN_T / 32) {
        int s = wtot[tid];
        int si = s;
        #pragma unroll
        for (int o = 1; o < SCAN_T / 32; o <<= 1) {
            int t = __shfl_up_sync(0xffu, si, o);
            if (tid >= o) si += t;
        }
        wtot[tid] = si - s;
    }
    __syncthreads();
    int excl = incl - v + wtot[wid] + s_boff;
    if (i < NN) {
        g_off[i] = excl;
        g_cur[i] = excl;
        if (i == NN - 1) g_off[NN] = excl + v;
    }
}

__global__ void k_fill(const int* __restrict__ src, const int* __restrict__ dst) {
    int e = blockIdx.x * blockDim.x + threadIdx.x;
    if (e < NE) {
        int d = dst[e];
        int pos = atomicAdd(&g_cur[d], 1);
        g_csr[pos] = src[e];
    }
}

// ---------------- HMMA GEMM: g = dinv * (A' @ W), fp16 A single, W hi/lo ----
// BN finalize fused: each block derives scale/shift from stats into smem.
#define SA    0
#define SB_HI 16384
#define SB_LO 32768
#define SC_OFF 49152
#define SH_OFF 49664
#define SM_TOTAL 50176

__device__ __forceinline__ void ldsm4(uint32_t& r0, uint32_t& r1, uint32_t& r2,
                                      uint32_t& r3, uint32_t addr) {
    asm volatile("ldmatrix.sync.aligned.m8n8.x4.shared.b16 {%0,%1,%2,%3}, [%4];"
                 : "=r"(r0), "=r"(r1), "=r"(r2), "=r"(r3) : "r"(addr));
}
__device__ __forceinline__ void mma16816(float* d, const uint32_t* a, const uint32_t* b) {
    asm volatile(
        "mma.sync.aligned.m16n8k16.row.col.f32.f16.f16.f32 "
        "{%0,%1,%2,%3}, {%4,%5,%6,%7}, {%8,%9}, {%0,%1,%2,%3};"
        : "+f"(d[0]), "+f"(d[1]), "+f"(d[2]), "+f"(d[3])
        : "r"(a[0]), "r"(a[1]), "r"(a[2]), "r"(a[3]), "r"(b[0]), "r"(b[1]));
}
#define CP_ASYNC16(dst, src) \
    asm volatile("cp.async.cg.shared.global [%0], [%1], 16;" :: "r"(dst), "l"(src))
#define CP_COMMIT() asm volatile("cp.async.commit_group;" ::: "memory")
#define CP_WAIT0() asm volatile("cp.async.wait_group 0;" ::: "memory")

__global__ void __launch_bounds__(256, 2) k_gemm_tc(int layer, const float* __restrict__ x,
                                                    const float* __restrict__ gamma,
                                                    const float* __restrict__ beta) {
    extern __shared__ char sm[];
    uint32_t sm_u = smem_to_u32(sm);
    int tid = threadIdx.x;
    int wid = tid >> 5, lane = tid & 31;

    float* scp = (float*)(sm + SC_OFF);
    float* shp = (float*)(sm + SH_OFF);
    if (layer > 0) {
        if (tid < DH) {
            float m = g_sum[(layer - 1) * DH + tid] * (1.f / NN);
            float var = g_sq[(layer - 1) * DH + tid] * (1.f / NN) - m * m;
            float rs = rsqrtf(var + BN_EPS);
            float scv = gamma[tid] * rs;
            scp[tid] = scv;
            shp[tid] = beta[tid] - m * scv;
        }
        __syncthreads();
    }

    int warp_m = (wid & 3) * 32;
    int warp_n = (wid >> 2) * 64;

    float acc[2][8][4];
    #pragma unroll
    for (int i = 0; i < 2; ++i)
        #pragma unroll
        for (int j = 0; j < 8; ++j)
            #pragma unroll
            for (int c = 0; c < 4; ++c) acc[i][j][c] = 0.f;

    int sub = lane >> 3, l7 = lane & 7;
    int a_r0 = warp_m + (sub & 1) * 8 + l7;
    int a_cadd = sub >> 1;
    int b_nsel = (sub >> 1) * 8 + l7;
    int b_cadd = sub & 1;

    int row = tid >> 1, hq = tid & 1;
    int gr = blockIdx.x * 128 + row;

    #pragma unroll
    for (int half = 0; half < 2; ++half) {
        {
            const char* wh = (const char*)(g_whi + layer * 16384 + half * 8192) + tid * 16;
            const char* wl = (const char*)(g_wlo + layer * 16384 + half * 8192) + tid * 16;
            uint32_t bh = sm_u + SB_HI + tid * 16;
            uint32_t bl = sm_u + SB_LO + tid * 16;
            #pragma unroll
            for (int i = 0; i < 4; ++i) {
                CP_ASYNC16(bh + i * 4096, wh + i * 4096);
                CP_ASYNC16(bl + i * 4096, wl + i * 4096);
            }
            CP_COMMIT();
        }
        // --- convert A' (32 values per thread) for this k-half, fp16 single
        if (gr < NN) {
            #pragma unroll
            for (int c8 = 0; c8 < 4; ++c8) {
                int lc = hq * 4 + c8;            // local kchunk 0..7
                int k0 = half * 64 + lc * 8;     // global k of first elem
                float f[8];
                if (layer == 0) {
                    float4 v0 = *(const float4*)(x + (size_t)gr * DH + k0);
                    float4 v1 = *(const float4*)(x + (size_t)gr * DH + k0 + 4);
                    f[0] = v0.x; f[1] = v0.y; f[2] = v0.z; f[3] = v0.w;
                    f[4] = v1.x; f[5] = v1.y; f[6] = v1.z; f[7] = v1.w;
                } else {
                    int4 u = *(const int4*)(g_hag + (size_t)gr * DH + k0);
                    float2 p0 = __half22float2(*(__half2*)&u.x);
                    float2 p1 = __half22float2(*(__half2*)&u.y);
                    float2 p2 = __half22float2(*(__half2*)&u.z);
                    float2 p3 = __half22float2(*(__half2*)&u.w);
                    f[0] = p0.x; f[1] = p0.y; f[2] = p1.x; f[3] = p1.y;
                    f[4] = p2.x; f[5] = p2.y; f[6] = p3.x; f[7] = p3.y;
                    #pragma unroll
                    for (int c = 0; c < 8; ++c)
                        f[c] = elu1(fmaf(f[c], scp[k0 + c], shp[k0 + c]));
                }
                uint32_t hp[4];
                #pragma unroll
                for (int p = 0; p < 4; ++p) {
                    __half2 h2 = __floats2half2_rn(f[p * 2], f[p * 2 + 1]);
                    hp[p] = *(uint32_t*)&h2;
                }
                *(int4*)(sm + SA + swz64(row, lc)) = make_int4(hp[0], hp[1], hp[2], hp[3]);
            }
        } else {
            int4 z = make_int4(0, 0, 0, 0);
            #pragma unroll
            for (int c8 = 0; c8 < 4; ++c8)
                *(int4*)(sm + SA + swz64(row, hq * 4 + c8)) = z;
        }
        CP_WAIT0();
        __syncthreads();

        // --- mainloop for this half: 4 k-steps, 2-pass (W hi + W lo)
        uint32_t aB = sm_u + SA;
        uint32_t bHi = sm_u + SB_HI, bLo = sm_u + SB_LO;
        #pragma unroll
        for (int ks = 0; ks < 4; ++ks) {
            int a_kc = ks * 2 + a_cadd;
            int b_kc = ks * 2 + b_cadd;

            uint32_t a[2][4];
            #pragma unroll
            for (int mf = 0; mf < 2; ++mf)
                ldsm4(a[mf][0], a[mf][1], a[mf][2], a[mf][3],
                      aB + swz64(a_r0 + mf * 16, a_kc));

            uint32_t bh[8][2];
            #pragma unroll
            for (int p = 0; p < 4; ++p)
                ldsm4(bh[p * 2][0], bh[p * 2][1], bh[p * 2 + 1][0], bh[p * 2 + 1][1],
                      bHi + swz64(warp_n + p * 16 + b_nsel, b_kc));

            #pragma unroll
            for (int mf = 0; mf < 2; ++mf)
                #pragma unroll
                for (int nf = 0; nf < 8; ++nf)
                    mma16816(acc[mf][nf], a[mf], bh[nf]);

            uint32_t bl[8][2];
            #pragma unroll
            for (int p = 0; p < 4; ++p)
                ldsm4(bl[p * 2][0], bl[p * 2][1], bl[p * 2 + 1][0], bl[p * 2 + 1][1],
                      bLo + swz64(warp_n + p * 16 + b_nsel, b_kc));

            #pragma unroll
            for (int mf = 0; mf < 2; ++mf)
                #pragma unroll
                for (int nf = 0; nf < 8; ++nf)
                    mma16816(acc[mf][nf], a[mf], bl[nf]);
        }
        if (half == 0) __syncthreads();
    }

    // --- epilogue: scale by dinv, convert fp16, store
    int qr = lane >> 2, qc = (lane & 3) * 2;
    #pragma unroll
    for (int mf = 0; mf < 2; ++mf) {
        int r0 = blockIdx.x * 128 + warp_m + mf * 16 + qr;
        int r1 = r0 + 8;
        float d0 = (r0 < NN) ? g_dinv[r0] : 0.f;
        float d1 = (r1 < NN) ? g_dinv[r1] : 0.f;
        #pragma unroll
        for (int nf = 0; nf < 8; ++nf) {
            int col = warp_n + nf * 8 + qc;
            if (r0 < NN) {
                __half2 o = __floats2half2_rn(acc[mf][nf][0] * d0, acc[mf][nf][1] * d0);
                *(__half2*)(g_gbuf + (size_t)r0 * DH + col) = o;
            }
            if (r1 < NN) {
                __half2 o = __floats2half2_rn(acc[mf][nf][2] * d1, acc[mf][nf][3] * d1);
                *(__half2*)(g_gbuf + (size_t)r1 * DH + col) = o;
            }
        }
    }
}

// ---------------- aggregation: fp16 gather, fp32 accumulate, fp16 h ----------
// layer 2 additionally zeroes the output buffer (replaces memset).
__device__ __forceinline__ void add_h4(float4& a, uint2 u) {
    float2 p0 = __half22float2(*(__half2*)&u.x);
    float2 p1 = __half22float2(*(__half2*)&u.y);
    a.x += p0.x; a.y += p0.y; a.z += p1.x; a.w += p1.y;
}

__global__ void __launch_bounds__(256) k_agg(int layer, const float* __restrict__ bias,
                                             float* __restrict__ out) {
    if (out) {
        int idx = blockIdx.x * 256 + threadIdx.x;
        if (idx < NG * DH) out[idx] = 0.f;
    }
    __shared__ float s_sum[DH];
    __shared__ float s_sq[DH];
    int tid = threadIdx.x;
    if (tid < DH) { s_sum[tid] = 0.f; s_sq[tid] = 0.f; }
    __syncthreads();

    int warp = tid >> 5, lane = tid & 31;
    int base = blockIdx.x * 32 + warp * 4;
    int f = lane * 4;
    float4 b = ((const float4*)bias)[lane];

    float ls0 = 0.f, ls1 = 0.f, ls2 = 0.f, ls3 = 0.f;
    float lq0 = 0.f, lq1 = 0.f, lq2 = 0.f, lq3 = 0.f;

    int nend = base + 4 < NN ? base + 4 : NN;
    for (int node = base; node < nend; ++node) {
        float4 a0 = make_float4(0.f, 0.f, 0.f, 0.f);
        float4 a1 = make_float4(0.f, 0.f, 0.f, 0.f);
        add_h4(a0, *(const uint2*)(g_gbuf + (size_t)node * DH + f));   // self
        int s = g_off[node], e2 = g_off[node + 1];
        int p = s;
        for (; p + 3 < e2; p += 4) {
            int s0 = g_csr[p], s1 = g_csr[p + 1], s2 = g_csr[p + 2], s3 = g_csr[p + 3];
            uint2 u0 = *(const uint2*)(g_gbuf + (size_t)s0 * DH + f);
            uint2 u1 = *(const uint2*)(g_gbuf + (size_t)s1 * DH + f);
            uint2 u2 = *(const uint2*)(g_gbuf + (size_t)s2 * DH + f);
            uint2 u3 = *(const uint2*)(g_gbuf + (size_t)s3 * DH + f);
            add_h4(a0, u0); add_h4(a1, u1); add_h4(a0, u2); add_h4(a1, u3);
        }
        for (; p < e2; ++p) {
            int s0 = g_csr[p];
            add_h4(a0, *(const uint2*)(g_gbuf + (size_t)s0 * DH + f));
        }
        float di = g_dinv[node];
        float4 h;
        h.x = fmaf(di, a0.x + a1.x, b.x);
        h.y = fmaf(di, a0.y + a1.y, b.y);
        h.z = fmaf(di, a0.z + a1.z, b.z);
        h.w = fmaf(di, a0.w + a1.w, b.w);
        __half2 o0 = __floats2half2_rn(h.x, h.y);
        __half2 o1 = __floats2half2_rn(h.z, h.w);
        uint2 ov;
        ov.x = *(uint32_t*)&o0;
        ov.y = *(uint32_t*)&o1;
        *(uint2*)(g_hag + (size_t)node * DH + f) = ov;

        ls0 += h.x; lq0 += h.x * h.x;
        ls1 += h.y; lq1 += h.y * h.y;
        ls2 += h.z; lq2 += h.z * h.z;
        ls3 += h.w; lq3 += h.w * h.w;
    }
    atomicAdd(&s_sum[f + 0], ls0); atomicAdd(&s_sq[f + 0], lq0);
    atomicAdd(&s_sum[f + 1], ls1); atomicAdd(&s_sq[f + 1], lq1);
    atomicAdd(&s_sum[f + 2], ls2); atomicAdd(&s_sq[f + 2], lq2);
    atomicAdd(&s_sum[f + 3], ls3); atomicAdd(&s_sq[f + 3], lq3);
    __syncthreads();
    if (tid < DH) {
        atomicAdd(&g_sum[layer * DH + tid], s_sum[tid]);
        atomicAdd(&g_sq[layer * DH + tid], s_sq[tid]);
    }
}

// ---------------- pooling: BN(from stats)+ELU, mean via pre-scaled atomics ---
__global__ void __launch_bounds__(256) k_pool(const int* __restrict__ bidx,
                                              const float* __restrict__ gamma,
                                              const float* __restrict__ beta,
                                              float* __restrict__ out) {
    int tid = threadIdx.x;
    int warp = (blockIdx.x * 8 + (tid >> 5));
    int base = warp * 8;
    if (base >= NN) return;
    int lane = tid & 31;
    int f = lane * 4;
    const int L2 = (NL - 1) * DH;
    float s[4], t[4];
    #pragma unroll
    for (int c = 0; c < 4; ++c) {
        float m = g_sum[L2 + f + c] * (1.f / NN);
        float var = g_sq[L2 + f + c] * (1.f / NN) - m * m;
        float rs = rsqrtf(var + BN_EPS);
        s[c] = gamma[f + c] * rs;
        t[c] = beta[f + c] - m * s[c];
    }

    float a0 = 0.f, a1 = 0.f, a2 = 0.f, a3 = 0.f;
    int cur = bidx[base];
    int end = base + 8 < NN ? base + 8 : NN;
    for (int n = base; n < end; ++n) {
        int gi = bidx[n];
        if (gi != cur) {
            float inv = 1.f / fmaxf((float)g_cnt[cur], 1.f);
            float* o = out + (size_t)cur * DH + f;
            atomicAdd(o + 0, a0 * inv); atomicAdd(o + 1, a1 * inv);
            atomicAdd(o + 2, a2 * inv); atomicAdd(o + 3, a3 * inv);
            a0 = a1 = a2 = a3 = 0.f;
            cur = gi;
        }
        uint2 u = *(const uint2*)(g_hag + (size_t)n * DH + f);
        float2 p0 = __half22float2(*(__half2*)&u.x);
        float2 p1 = __half22float2(*(__half2*)&u.y);
        a0 += elu1(fmaf(p0.x, s[0], t[0]));
        a1 += elu1(fmaf(p0.y, s[1], t[1]));
        a2 += elu1(fmaf(p1.x, s[2], t[2]));
        a3 += elu1(fmaf(p1.y, s[3], t[3]));
    }
    float inv = 1.f / fmaxf((float)g_cnt[cur], 1.f);
    float* o = out + (size_t)cur * DH + f;
    atomicAdd(o + 0, a0 * inv); atomicAdd(o + 1, a1 * inv);
    atomicAdd(o + 2, a2 * inv); atomicAdd(o + 3, a3 * inv);
}

// ---------------- launch ----------------
extern "C" void kernel_launch(void* const* d_in, const int* in_sizes, int n_in,
                              void* d_out, int out_size) {
    const float* x      = (const float*)d_in[0];
    const float* Ws     = (const float*)d_in[1];
    const float* bs     = (const float*)d_in[2];
    const float* gammas = (const float*)d_in[3];
    const float* betas  = (const float*)d_in[4];
    const int*   ei     = (const int*)d_in[5];
    const int*   bidx   = (const int*)d_in[6];
    float*       out    = (float*)d_out;

    const int* src = ei;
    const int* dst = ei + NE;

    cudaFuncSetAttribute(k_gemm_tc, cudaFuncAttributeMaxDynamicSharedMemorySize, SM_TOTAL);

    int gemm_grid = (NN + 127) / 128;
    int agg_grid = (NN + 31) / 32;

    k_init_all<<<(NN + 255) / 256, 256>>>(Ws);                      // 1
    k_deg<<<(NE + 255) / 256, 256>>>(dst, bidx);                    // 2
    k_bsum<<<SCAN_NB, SCAN_T>>>();                                  // 3 (+dinv)
    k_gemm_tc<<<gemm_grid, 256, SM_TOTAL>>>(0, x, gammas, betas);   // 4 <- ncu slot
    k_lscan<<<SCAN_NB, SCAN_T>>>();                                 // 5 (+bscan)
    k_fill<<<(NE + 255) / 256, 256>>>(src, dst);                    // 6

    k_agg<<<agg_grid, 256>>>(0, bs, nullptr);                       // 7
    k_gemm_tc<<<gemm_grid, 256, SM_TOTAL>>>(1, x, gammas + DH, betas + DH);
    k_agg<<<agg_grid, 256>>>(1, bs + DH, nullptr);
    k_gemm_tc<<<gemm_grid, 256, SM_TOTAL>>>(2, x, gammas + 2 * DH, betas + 2 * DH);
    k_agg<<<agg_grid, 256>>>(2, bs + 2 * DH, out);                  // zeroes out

    int pool_grid = (NN + 63) / 64;
    k_pool<<<pool_grid, 256>>>(bidx, gammas + 2 * DH, betas + 2 * DH, out);
}

// round 12
// speedup vs baseline: 1.6374x; 1.0491x over previous
#include <cuda_runtime.h>
#include <cuda_fp16.h>
#include <math.h>
#include <stdint.h>

#define NN 50000
#define NE 640000
#define DH 128
#define NG 1024
#define NL 3
#define BN_EPS 1e-5f

#define SCAN_T 256
#define SCAN_NB ((NN + SCAN_T - 1) / SCAN_T)   // 196

__device__ __forceinline__ uint32_t smem_to_u32(const void* p) {
    uint32_t a;
    asm("{ .reg .u64 t; cvta.to.shared.u64 t, %1; cvt.u32.u64 %0, t; }" : "=r"(a) : "l"(p));
    return a;
}

// ---------------- scratch ----------------
__device__ int   g_deg[NN];
__device__ int   g_off[NN + 1];
__device__ int   g_cur[NN];
__device__ float g_dinv[NN];
__device__ int   g_csr[NE];
__device__ int   g_bsum[SCAN_NB];
__device__ __half g_gbuf[(size_t)NN * DH];     // fp16 messages
__device__ __half g_hag[(size_t)NN * DH];      // fp16 aggregated h
__device__ float g_sum[NL * DH];
__device__ float g_sq[NL * DH];
__device__ int   g_cnt[NG];
// W^T single fp16; per layer one 32KB swizzled tile
__device__ unsigned short g_whi[NL * 16384];

__device__ __forceinline__ float elu1(float v) {
    return v > 0.f ? v : (__expf(v) - 1.f);
}

// swizzled byte offset within a 128row x 128k fp16 (32KB) tile (256B rows)
__device__ __forceinline__ int swz_off(int r, int kchunk) {
    return r * 256 + ((kchunk ^ (r & 7)) << 4);
}

// ---------------- launch 1: init everything + W convert ----------------
__global__ void k_init_all(const float* __restrict__ Ws) {
    int i = blockIdx.x * 256 + threadIdx.x;
    if (i < NN) g_deg[i] = 0;
    if (i < NL * DH) { g_sum[i] = 0.f; g_sq[i] = 0.f; }
    if (i < NG) g_cnt[i] = 0;
    if (i < NL * 16384) {
        int l = i >> 14;
        int rem = i & 16383;
        int n = rem & 127;
        int k = rem >> 7;
        float w = Ws[(size_t)l * 16384 + k * 128 + n];
        int off = swz_off(n, k >> 3) + (k & 7) * 2;
        g_whi[l * 16384 + (off >> 1)] = __half_as_ushort(__float2half_rn(w));
    }
}

// ---------------- launch 2: degree histogram + graph counts ----------------
__global__ void k_deg(const int* __restrict__ dst, const int* __restrict__ bidx) {
    int e = blockIdx.x * blockDim.x + threadIdx.x;
    if (e < NE) atomicAdd(&g_deg[dst[e]], 1);
    if (e < NN) atomicAdd(&g_cnt[bidx[e]], 1);
}

// ---------------- launch 3: block sums + dinv ----------------
__global__ void __launch_bounds__(SCAN_T) k_bsum() {
    int i = blockIdx.x * SCAN_T + threadIdx.x;
    int v = (i < NN) ? g_deg[i] : 0;
    if (i < NN) g_dinv[i] = rsqrtf((float)(v + 1));   // +1 self loop
    #pragma unroll
    for (int o = 16; o; o >>= 1) v += __shfl_down_sync(0xffffffffu, v, o);
    __shared__ int ws[SCAN_T / 32];
    if ((threadIdx.x & 31) == 0) ws[threadIdx.x >> 5] = v;
    __syncthreads();
    if (threadIdx.x < SCAN_T / 32) {
        int s = ws[threadIdx.x];
        #pragma unroll
        for (int o = SCAN_T / 64; o; o >>= 1) s += __shfl_down_sync(0xffu, s, o);
        if (threadIdx.x == 0) g_bsum[blockIdx.x] = s;
    }
}

// ---------------- local scan with self-computed block offset ----------------
__global__ void __launch_bounds__(SCAN_T) k_lscan() {
    int tid = threadIdx.x;
    int lane = tid & 31, wid = tid >> 5;
    int bid = blockIdx.x;

    __shared__ int s_boff;
    __shared__ int wred[SCAN_T / 32];
    {
        int bv = (tid < bid) ? g_bsum[tid] : 0;
        #pragma unroll
        for (int o = 16; o; o >>= 1) bv += __shfl_down_sync(0xffffffffu, bv, o);
        if (lane == 0) wred[wid] = bv;
        __syncthreads();
        if (tid == 0) {
            int s = 0;
            #pragma unroll
            for (int w = 0; w < SCAN_T / 32; ++w) s += wred[w];
            s_boff = s;
        }
        __syncthreads();
    }

    int i = bid * SCAN_T + tid;
    int v = (i < NN) ? g_deg[i] : 0;
    int incl = v;
    #pragma unroll
    for (int o = 1; o < 32; o <<= 1) {
        int t = __shfl_up_sync(0xffffffffu, incl, o);
        if (lane >= o) incl += t;
    }
    __shared__ int wtot[SCAN_T / 32];
    if (lane == 31) wtot[wid] = incl;
    __syncthreads();
    if (tid < SCAN_T / 32) {
        int s = wtot[tid];
        int si = s;
        #pragma unroll
        for (int o = 1; o < SCAN_T / 32; o <<= 1) {
            int t = __shfl_up_sync(0xffu, si, o);
            if (tid >= o) si += t;
        }
        wtot[tid] = si - s;
    }
    __syncthreads();
    int excl = incl - v + wtot[wid] + s_boff;
    if (i < NN) {
        g_off[i] = excl;
        g_cur[i] = excl;
        if (i == NN - 1) g_off[NN] = excl + v;
    }
}

__global__ void k_fill(const int* __restrict__ src, const int* __restrict__ dst) {
    int e = blockIdx.x * blockDim.x + threadIdx.x;
    if (e < NE) {
        int d = dst[e];
        int pos = atomicAdd(&g_cur[d], 1);
        g_csr[pos] = src[e];
    }
}

// ---------------- HMMA GEMM: g = dinv * (A' @ W), pure fp16, single pass ----
#define SA    0
#define SB    32768
#define SC_OFF 65536
#define SH_OFF 66048
#define SM_TOTAL 66560

__device__ __forceinline__ void ldsm4(uint32_t& r0, uint32_t& r1, uint32_t& r2,
                                      uint32_t& r3, uint32_t addr) {
    asm volatile("ldmatrix.sync.aligned.m8n8.x4.shared.b16 {%0,%1,%2,%3}, [%4];"
                 : "=r"(r0), "=r"(r1), "=r"(r2), "=r"(r3) : "r"(addr));
}
__device__ __forceinline__ void mma16816(float* d, const uint32_t* a, const uint32_t* b) {
    asm volatile(
        "mma.sync.aligned.m16n8k16.row.col.f32.f16.f16.f32 "
        "{%0,%1,%2,%3}, {%4,%5,%6,%7}, {%8,%9}, {%0,%1,%2,%3};"
        : "+f"(d[0]), "+f"(d[1]), "+f"(d[2]), "+f"(d[3])
        : "r"(a[0]), "r"(a[1]), "r"(a[2]), "r"(a[3]), "r"(b[0]), "r"(b[1]));
}
#define CP_ASYNC16(dst, src) \
    asm volatile("cp.async.cg.shared.global [%0], [%1], 16;" :: "r"(dst), "l"(src))
#define CP_COMMIT() asm volatile("cp.async.commit_group;" ::: "memory")
#define CP_WAIT0() asm volatile("cp.async.wait_group 0;" ::: "memory")

__global__ void __launch_bounds__(256, 2) k_gemm_tc(int layer, const float* __restrict__ x,
                                                    const float* __restrict__ gamma,
                                                    const float* __restrict__ beta) {
    extern __shared__ char sm[];
    uint32_t sm_u = smem_to_u32(sm);
    int tid = threadIdx.x;
    int wid = tid >> 5, lane = tid & 31;

    // --- B tile (32KB) via cp.async
    {
        const char* wh = (const char*)(g_whi + layer * 16384) + tid * 16;
        uint32_t bh = sm_u + SB + tid * 16;
        #pragma unroll
        for (int i = 0; i < 8; ++i)
            CP_ASYNC16(bh + i * 4096, wh + i * 4096);
        CP_COMMIT();
    }

    // --- BN scale/shift into smem
    float* scp = (float*)(sm + SC_OFF);
    float* shp = (float*)(sm + SH_OFF);
    if (layer > 0 && tid < DH) {
        float m = g_sum[(layer - 1) * DH + tid] * (1.f / NN);
        float var = g_sq[(layer - 1) * DH + tid] * (1.f / NN) - m * m;
        float rs = rsqrtf(var + BN_EPS);
        float scv = gamma[tid] * rs;
        scp[tid] = scv;
        shp[tid] = beta[tid] - m * scv;
    }
    if (layer > 0) __syncthreads();

    // --- convert A' half-row per thread (fused BN+ELU for layer>0)
    {
        int row = tid >> 1, hq = tid & 1;
        int gr = blockIdx.x * 128 + row;
        if (gr < NN) {
            #pragma unroll
            for (int c8 = 0; c8 < 8; ++c8) {
                int kc = hq * 8 + c8;
                int k0 = kc * 8;
                float f[8];
                if (layer == 0) {
                    float4 v0 = *(const float4*)(x + (size_t)gr * DH + k0);
                    float4 v1 = *(const float4*)(x + (size_t)gr * DH + k0 + 4);
                    f[0] = v0.x; f[1] = v0.y; f[2] = v0.z; f[3] = v0.w;
                    f[4] = v1.x; f[5] = v1.y; f[6] = v1.z; f[7] = v1.w;
                } else {
                    int4 u = *(const int4*)(g_hag + (size_t)gr * DH + k0);
                    float2 p0 = __half22float2(*(__half2*)&u.x);
                    float2 p1 = __half22float2(*(__half2*)&u.y);
                    float2 p2 = __half22float2(*(__half2*)&u.z);
                    float2 p3 = __half22float2(*(__half2*)&u.w);
                    f[0] = p0.x; f[1] = p0.y; f[2] = p1.x; f[3] = p1.y;
                    f[4] = p2.x; f[5] = p2.y; f[6] = p3.x; f[7] = p3.y;
                    #pragma unroll
                    for (int c = 0; c < 8; ++c)
                        f[c] = elu1(fmaf(f[c], scp[k0 + c], shp[k0 + c]));
                }
                uint32_t hp[4];
                #pragma unroll
                for (int p = 0; p < 4; ++p) {
                    __half2 h2 = __floats2half2_rn(f[p * 2], f[p * 2 + 1]);
                    hp[p] = *(uint32_t*)&h2;
                }
                *(int4*)(sm + SA + swz_off(row, kc)) = make_int4(hp[0], hp[1], hp[2], hp[3]);
            }
        } else {
            int4 z = make_int4(0, 0, 0, 0);
            #pragma unroll
            for (int c8 = 0; c8 < 8; ++c8)
                *(int4*)(sm + SA + swz_off(row, hq * 8 + c8)) = z;
        }
    }
    CP_WAIT0();
    __syncthreads();

    int warp_m = (wid & 3) * 32;
    int warp_n = (wid >> 2) * 64;

    float acc[2][8][4];
    #pragma unroll
    for (int i = 0; i < 2; ++i)
        #pragma unroll
        for (int j = 0; j < 8; ++j)
            #pragma unroll
            for (int c = 0; c < 4; ++c) acc[i][j][c] = 0.f;

    int sub = lane >> 3, l7 = lane & 7;
    int a_r0 = warp_m + (sub & 1) * 8 + l7;
    int a_cadd = sub >> 1;
    int b_nsel = (sub >> 1) * 8 + l7;
    int b_cadd = sub & 1;

    uint32_t aB = sm_u + SA, bB = sm_u + SB;
    #pragma unroll
    for (int ks = 0; ks < 8; ++ks) {
        int a_kc = ks * 2 + a_cadd;
        int b_kc = ks * 2 + b_cadd;

        uint32_t a[2][4];
        #pragma unroll
        for (int mf = 0; mf < 2; ++mf)
            ldsm4(a[mf][0], a[mf][1], a[mf][2], a[mf][3],
                  aB + swz_off(a_r0 + mf * 16, a_kc));

        uint32_t b[8][2];
        #pragma unroll
        for (int p = 0; p < 4; ++p)
            ldsm4(b[p * 2][0], b[p * 2][1], b[p * 2 + 1][0], b[p * 2 + 1][1],
                  bB + swz_off(warp_n + p * 16 + b_nsel, b_kc));

        #pragma unroll
        for (int mf = 0; mf < 2; ++mf)
            #pragma unroll
            for (int nf = 0; nf < 8; ++nf)
                mma16816(acc[mf][nf], a[mf], b[nf]);
    }

    // --- epilogue: scale by dinv, convert fp16, store
    int qr = lane >> 2, qc = (lane & 3) * 2;
    #pragma unroll
    for (int mf = 0; mf < 2; ++mf) {
        int r0 = blockIdx.x * 128 + warp_m + mf * 16 + qr;
        int r1 = r0 + 8;
        float d0 = (r0 < NN) ? g_dinv[r0] : 0.f;
        float d1 = (r1 < NN) ? g_dinv[r1] : 0.f;
        #pragma unroll
        for (int nf = 0; nf < 8; ++nf) {
            int col = warp_n + nf * 8 + qc;
            if (r0 < NN) {
                __half2 o = __floats2half2_rn(acc[mf][nf][0] * d0, acc[mf][nf][1] * d0);
                *(__half2*)(g_gbuf + (size_t)r0 * DH + col) = o;
            }
            if (r1 < NN) {
                __half2 o = __floats2half2_rn(acc[mf][nf][2] * d1, acc[mf][nf][3] * d1);
                *(__half2*)(g_gbuf + (size_t)r1 * DH + col) = o;
            }
        }
    }
}

// ---------------- aggregation: fp16 gather, fp32 accumulate, fp16 h ----------
__device__ __forceinline__ void add_h4(float4& a, uint2 u) {
    float2 p0 = __half22float2(*(__half2*)&u.x);
    float2 p1 = __half22float2(*(__half2*)&u.y);
    a.x += p0.x; a.y += p0.y; a.z += p1.x; a.w += p1.y;
}

__global__ void __launch_bounds__(256) k_agg(int layer, const float* __restrict__ bias,
                                             float* __restrict__ out) {
    if (out) {
        int idx = blockIdx.x * 256 + threadIdx.x;
        if (idx < NG * DH) out[idx] = 0.f;
    }
    __shared__ float s_sum[DH];
    __shared__ float s_sq[DH];
    int tid = threadIdx.x;
    if (tid < DH) { s_sum[tid] = 0.f; s_sq[tid] = 0.f; }
    __syncthreads();

    int warp = tid >> 5, lane = tid & 31;
    int base = blockIdx.x * 32 + warp * 4;
    int f = lane * 4;
    float4 b = ((const float4*)bias)[lane];

    float ls0 = 0.f, ls1 = 0.f, ls2 = 0.f, ls3 = 0.f;
    float lq0 = 0.f, lq1 = 0.f, lq2 = 0.f, lq3 = 0.f;

    int nend = base + 4 < NN ? base + 4 : NN;
    for (int node = base; node < nend; ++node) {
        float4 a0 = make_float4(0.f, 0.f, 0.f, 0.f);
        float4 a1 = make_float4(0.f, 0.f, 0.f, 0.f);
        add_h4(a0, *(const uint2*)(g_gbuf + (size_t)node * DH + f));   // self
        int s = g_off[node], e2 = g_off[node + 1];
        int p = s;
        for (; p + 3 < e2; p += 4) {
            int s0 = g_csr[p], s1 = g_csr[p + 1], s2 = g_csr[p + 2], s3 = g_csr[p + 3];
            uint2 u0 = *(const uint2*)(g_gbuf + (size_t)s0 * DH + f);
            uint2 u1 = *(const uint2*)(g_gbuf + (size_t)s1 * DH + f);
            uint2 u2 = *(const uint2*)(g_gbuf + (size_t)s2 * DH + f);
            uint2 u3 = *(const uint2*)(g_gbuf + (size_t)s3 * DH + f);
            add_h4(a0, u0); add_h4(a1, u1); add_h4(a0, u2); add_h4(a1, u3);
        }
        for (; p < e2; ++p) {
            int s0 = g_csr[p];
            add_h4(a0, *(const uint2*)(g_gbuf + (size_t)s0 * DH + f));
        }
        float di = g_dinv[node];
        float4 h;
        h.x = fmaf(di, a0.x + a1.x, b.x);
        h.y = fmaf(di, a0.y + a1.y, b.y);
        h.z = fmaf(di, a0.z + a1.z, b.z);
        h.w = fmaf(di, a0.w + a1.w, b.w);
        __half2 o0 = __floats2half2_rn(h.x, h.y);
        __half2 o1 = __floats2half2_rn(h.z, h.w);
        uint2 ov;
        ov.x = *(uint32_t*)&o0;
        ov.y = *(uint32_t*)&o1;
        *(uint2*)(g_hag + (size_t)node * DH + f) = ov;

        ls0 += h.x; lq0 += h.x * h.x;
        ls1 += h.y; lq1 += h.y * h.y;
        ls2 += h.z; lq2 += h.z * h.z;
        ls3 += h.w; lq3 += h.w * h.w;
    }
    atomicAdd(&s_sum[f + 0], ls0); atomicAdd(&s_sq[f + 0], lq0);
    atomicAdd(&s_sum[f + 1], ls1); atomicAdd(&s_sq[f + 1], lq1);
    atomicAdd(&s_sum[f + 2], ls2); atomicAdd(&s_sq[f + 2], lq2);
    atomicAdd(&s_sum[f + 3], ls3); atomicAdd(&s_sq[f + 3], lq3);
    __syncthreads();
    if (tid < DH) {
        atomicAdd(&g_sum[layer * DH + tid], s_sum[tid]);
        atomicAdd(&g_sq[layer * DH + tid], s_sq[tid]);
    }
}

// ---------------- pooling: BN(from stats)+ELU, mean via pre-scaled atomics ---
__global__ void __launch_bounds__(256) k_pool(const int* __restrict__ bidx,
                                              const float* __restrict__ gamma,
                                              const float* __restrict__ beta,
                                              float* __restrict__ out) {
    int tid = threadIdx.x;
    int warp = (blockIdx.x * 8 + (tid >> 5));
    int base = warp * 8;
    if (base >= NN) return;
    int lane = tid & 31;
    int f = lane * 4;
    const int L2 = (NL - 1) * DH;
    float s[4], t[4];
    #pragma unroll
    for (int c = 0; c < 4; ++c) {
        float m = g_sum[L2 + f + c] * (1.f / NN);
        float var = g_sq[L2 + f + c] * (1.f / NN) - m * m;
        float rs = rsqrtf(var + BN_EPS);
        s[c] = gamma[f + c] * rs;
        t[c] = beta[f + c] - m * s[c];
    }

    float a0 = 0.f, a1 = 0.f, a2 = 0.f, a3 = 0.f;
    int cur = bidx[base];
    int end = base + 8 < NN ? base + 8 : NN;
    for (int n = base; n < end; ++n) {
        int gi = bidx[n];
        if (gi != cur) {
            float inv = 1.f / fmaxf((float)g_cnt[cur], 1.f);
            float* o = out + (size_t)cur * DH + f;
            atomicAdd(o + 0, a0 * inv); atomicAdd(o + 1, a1 * inv);
            atomicAdd(o + 2, a2 * inv); atomicAdd(o + 3, a3 * inv);
            a0 = a1 = a2 = a3 = 0.f;
            cur = gi;
        }
        uint2 u = *(const uint2*)(g_hag + (size_t)n * DH + f);
        float2 p0 = __half22float2(*(__half2*)&u.x);
        float2 p1 = __half22float2(*(__half2*)&u.y);
        a0 += elu1(fmaf(p0.x, s[0], t[0]));
        a1 += elu1(fmaf(p0.y, s[1], t[1]));
        a2 += elu1(fmaf(p1.x, s[2], t[2]));
        a3 += elu1(fmaf(p1.y, s[3], t[3]));
    }
    float inv = 1.f / fmaxf((float)g_cnt[cur], 1.f);
    float* o = out + (size_t)cur * DH + f;
    atomicAdd(o + 0, a0 * inv); atomicAdd(o + 1, a1 * inv);
    atomicAdd(o + 2, a2 * inv); atomicAdd(o + 3, a3 * inv);
}

// ---------------- launch ----------------
extern "C" void kernel_launch(void* const* d_in, const int* in_sizes, int n_in,
                              void* d_out, int out_size) {
    const float* x      = (const float*)d_in[0];
    const float* Ws     = (const float*)d_in[1];
    const float* bs     = (const float*)d_in[2];
    const float* gammas = (const float*)d_in[3];
    const float* betas  = (const float*)d_in[4];
    const int*   ei     = (const int*)d_in[5];
    const int*   bidx   = (const int*)d_in[6];
    float*       out    = (float*)d_out;

    const int* src = ei;
    const int* dst = ei + NE;

    cudaFuncSetAttribute(k_gemm_tc, cudaFuncAttributeMaxDynamicSharedMemorySize, SM_TOTAL);

    int gemm_grid = (NN + 127) / 128;
    int agg_grid = (NN + 31) / 32;

    k_init_all<<<(NN + 255) / 256, 256>>>(Ws);                      // 1
    k_deg<<<(NE + 255) / 256, 256>>>(dst, bidx);                    // 2
    k_bsum<<<SCAN_NB, SCAN_T>>>();                                  // 3 (+dinv)
    k_gemm_tc<<<gemm_grid, 256, SM_TOTAL>>>(0, x, gammas, betas);   // 4 <- ncu slot
    k_lscan<<<SCAN_NB, SCAN_T>>>();                                 // 5 (+bscan)
    k_fill<<<(NE + 255) / 256, 256>>>(src, dst);                    // 6

    k_agg<<<agg_grid, 256>>>(0, bs, nullptr);                       // 7
    k_gemm_tc<<<gemm_grid, 256, SM_TOTAL>>>(1, x, gammas + DH, betas + DH);
    k_agg<<<agg_grid, 256>>>(1, bs + DH, nullptr);
    k_gemm_tc<<<gemm_grid, 256, SM_TOTAL>>>(2, x, gammas + 2 * DH, betas + 2 * DH);
    k_agg<<<agg_grid, 256>>>(2, bs + 2 * DH, out);                  // zeroes out

    int pool_grid = (NN + 63) / 64;
    k_pool<<<pool_grid, 256>>>(bidx, gammas + 2 * DH, betas + 2 * DH, out);
}

// round 14
// speedup vs baseline: 1.7053x; 1.0414x over previous
#include <cuda_runtime.h>
#include <cuda_fp16.h>
#include <math.h>
#include <stdint.h>

#define NN 50000
#define NE 640000
#define DH 128
#define NG 1024
#define NL 3
#define BN_EPS 1e-5f

#define SCAN_T 256
#define SCAN_NB ((NN + SCAN_T - 1) / SCAN_T)   // 196

#define GEMM_TILES ((NN + 127) / 128)          // 391
#define GEMM_GRID 296                          // 2 CTAs x 148 SMs resident

__device__ __forceinline__ uint32_t smem_to_u32(const void* p) {
    uint32_t a;
    asm("{ .reg .u64 t; cvta.to.shared.u64 t, %1; cvt.u32.u64 %0, t; }" : "=r"(a) : "l"(p));
    return a;
}

// ---------------- scratch ----------------
__device__ int   g_deg[NN];
__device__ int   g_off[NN + 1];
__device__ int   g_cur[NN];
__device__ float g_dinv[NN];
__device__ int   g_csr[NE];
__device__ int   g_bsum[SCAN_NB];
__device__ __half g_gbuf[(size_t)NN * DH];     // fp16 messages
__device__ __half g_hag[(size_t)NN * DH];      // fp16 aggregated h
__device__ float g_sum[NL * DH];
__device__ float g_sq[NL * DH];
__device__ int   g_cnt[NG];
__device__ unsigned short g_whi[NL * 16384];   // W^T fp16, swizzled 32KB/layer

__device__ __forceinline__ float elu1(float v) {
    return v > 0.f ? v : (__expf(v) - 1.f);
}

__device__ __forceinline__ int swz_off(int r, int kchunk) {
    return r * 256 + ((kchunk ^ (r & 7)) << 4);
}

// ---------------- launch 1: init everything + W convert ----------------
__global__ void k_init_all(const float* __restrict__ Ws) {
    int i = blockIdx.x * 256 + threadIdx.x;
    if (i < NN) g_deg[i] = 0;
    if (i < NL * DH) { g_sum[i] = 0.f; g_sq[i] = 0.f; }
    if (i < NG) g_cnt[i] = 0;
    if (i < NL * 16384) {
        int l = i >> 14;
        int rem = i & 16383;
        int n = rem & 127;
        int k = rem >> 7;
        float w = Ws[(size_t)l * 16384 + k * 128 + n];
        int off = swz_off(n, k >> 3) + (k & 7) * 2;
        g_whi[l * 16384 + (off >> 1)] = __half_as_ushort(__float2half_rn(w));
    }
}

// ---------------- launch 2: degree histogram + graph counts ----------------
__global__ void k_deg(const int* __restrict__ dst, const int* __restrict__ bidx) {
    int e = blockIdx.x * blockDim.x + threadIdx.x;
    if (e < NE) atomicAdd(&g_deg[dst[e]], 1);
    if (e < NN) atomicAdd(&g_cnt[bidx[e]], 1);
}

// ---------------- launch 3: block sums + dinv ----------------
__global__ void __launch_bounds__(SCAN_T) k_bsum() {
    int i = blockIdx.x * SCAN_T + threadIdx.x;
    int v = (i < NN) ? g_deg[i] : 0;
    if (i < NN) g_dinv[i] = rsqrtf((float)(v + 1));   // +1 self loop
    #pragma unroll
    for (int o = 16; o; o >>= 1) v += __shfl_down_sync(0xffffffffu, v, o);
    __shared__ int ws[SCAN_T / 32];
    if ((threadIdx.x & 31) == 0) ws[threadIdx.x >> 5] = v;
    __syncthreads();
    if (threadIdx.x < SCAN_T / 32) {
        int s = ws[threadIdx.x];
        #pragma unroll
        for (int o = SCAN_T / 64; o; o >>= 1) s += __shfl_down_sync(0xffu, s, o);
        if (threadIdx.x == 0) g_bsum[blockIdx.x] = s;
    }
}

// ---------------- local scan with self-computed block offset ----------------
__global__ void __launch_bounds__(SCAN_T) k_lscan() {
    int tid = threadIdx.x;
    int lane = tid & 31, wid = tid >> 5;
    int bid = blockIdx.x;

    __shared__ int s_boff;
    __shared__ int wred[SCAN_T / 32];
    {
        int bv = (tid < bid) ? g_bsum[tid] : 0;
        #pragma unroll
        for (int o = 16; o; o >>= 1) bv += __shfl_down_sync(0xffffffffu, bv, o);
        if (lane == 0) wred[wid] = bv;
        __syncthreads();
        if (tid == 0) {
            int s = 0;
            #pragma unroll
            for (int w = 0; w < SCAN_T / 32; ++w) s += wred[w];
            s_boff = s;
        }
        __syncthreads();
    }

    int i = bid * SCAN_T + tid;
    int v = (i < NN) ? g_deg[i] : 0;
    int incl = v;
    #pragma unroll
    for (int o = 1; o < 32; o <<= 1) {
        int t = __shfl_up_sync(0xffffffffu, incl, o);
        if (lane >= o) incl += t;
    }
    __shared__ int wtot[SCAN_T / 32];
    if (lane == 31) wtot[wid] = incl;
    __syncthreads();
    if (tid < SCAN_T / 32) {
        int s = wtot[tid];
        int si = s;
        #pragma unroll
        for (int o = 1; o < SCAN_T / 32; o <<= 1) {
            int t = __shfl_up_sync(0xffu, si, o);
            if (tid >= o) si += t;
        }
        wtot[tid] = si - s;
    }
    __syncthreads();
    int excl = incl - v + wtot[wid] + s_boff;
    if (i < NN) {
        g_off[i] = excl;
        g_cur[i] = excl;
        if (i == NN - 1) g_off[NN] = excl + v;
    }
}

__global__ void k_fill(const int* __restrict__ src, const int* __restrict__ dst) {
    int e = blockIdx.x * blockDim.x + threadIdx.x;
    if (e < NE) {
        int d = dst[e];
        int pos = atomicAdd(&g_cur[d], 1);
        g_csr[pos] = src[e];
    }
}

// ---------------- HMMA GEMM: persistent 296-CTA, pure fp16, single pass ----
#define SA    0
#define SB    32768
#define SC_OFF 65536
#define SH_OFF 66048
#define SM_TOTAL 66560

__device__ __forceinline__ void ldsm4(uint32_t& r0, uint32_t& r1, uint32_t& r2,
                                      uint32_t& r3, uint32_t addr) {
    asm volatile("ldmatrix.sync.aligned.m8n8.x4.shared.b16 {%0,%1,%2,%3}, [%4];"
                 : "=r"(r0), "=r"(r1), "=r"(r2), "=r"(r3) : "r"(addr));
}
__device__ __forceinline__ void mma16816(float* d, const uint32_t* a, const uint32_t* b) {
    asm volatile(
        "mma.sync.aligned.m16n8k16.row.col.f32.f16.f16.f32 "
        "{%0,%1,%2,%3}, {%4,%5,%6,%7}, {%8,%9}, {%0,%1,%2,%3};"
        : "+f"(d[0]), "+f"(d[1]), "+f"(d[2]), "+f"(d[3])
        : "r"(a[0]), "r"(a[1]), "r"(a[2]), "r"(a[3]), "r"(b[0]), "r"(b[1]));
}
#define CP_ASYNC16(dst, src) \
    asm volatile("cp.async.cg.shared.global [%0], [%1], 16;" :: "r"(dst), "l"(src))
#define CP_COMMIT() asm volatile("cp.async.commit_group;" ::: "memory")
#define CP_WAIT0() asm volatile("cp.async.wait_group 0;" ::: "memory")

__global__ void __launch_bounds__(256, 2) k_gemm_tc(int layer, const float* __restrict__ x,
                                                    const float* __restrict__ gamma,
                                                    const float* __restrict__ beta) {
    extern __shared__ char sm[];
    uint32_t sm_u = smem_to_u32(sm);
    int tid = threadIdx.x;
    int wid = tid >> 5, lane = tid & 31;

    // --- once per CTA: B tile (32KB) via cp.async
    {
        const char* wh = (const char*)(g_whi + layer * 16384) + tid * 16;
        uint32_t bh = sm_u + SB + tid * 16;
        #pragma unroll
        for (int i = 0; i < 8; ++i)
            CP_ASYNC16(bh + i * 4096, wh + i * 4096);
        CP_COMMIT();
    }

    // --- once per CTA: BN scale/shift into smem
    float* scp = (float*)(sm + SC_OFF);
    float* shp = (float*)(sm + SH_OFF);
    if (layer > 0 && tid < DH) {
        float m = g_sum[(layer - 1) * DH + tid] * (1.f / NN);
        float var = g_sq[(layer - 1) * DH + tid] * (1.f / NN) - m * m;
        float rs = rsqrtf(var + BN_EPS);
        float scv = gamma[tid] * rs;
        scp[tid] = scv;
        shp[tid] = beta[tid] - m * scv;
    }
    CP_WAIT0();
    __syncthreads();   // publish scp/shp (and B tile) before any tile's conversion

    int warp_m = (wid & 3) * 32;
    int warp_n = (wid >> 2) * 64;
    int sub = lane >> 3, l7 = lane & 7;
    int a_r0 = warp_m + (sub & 1) * 8 + l7;
    int a_cadd = sub >> 1;
    int b_nsel = (sub >> 1) * 8 + l7;
    int b_cadd = sub & 1;
    int row = tid >> 1, hq = tid & 1;
    uint32_t aB = sm_u + SA, bB = sm_u + SB;

    for (int tile = blockIdx.x; tile < GEMM_TILES; tile += GEMM_GRID) {
        // --- convert A' half-row per thread (fused BN+ELU for layer>0)
        int gr = tile * 128 + row;
        if (gr < NN) {
            #pragma unroll
            for (int c8 = 0; c8 < 8; ++c8) {
                int kc = hq * 8 + c8;
                int k0 = kc * 8;
                float f[8];
                if (layer == 0) {
                    float4 v0 = *(const float4*)(x + (size_t)gr * DH + k0);
                    float4 v1 = *(const float4*)(x + (size_t)gr * DH + k0 + 4);
                    f[0] = v0.x; f[1] = v0.y; f[2] = v0.z; f[3] = v0.w;
                    f[4] = v1.x; f[5] = v1.y; f[6] = v1.z; f[7] = v1.w;
                } else {
                    int4 u = *(const int4*)(g_hag + (size_t)gr * DH + k0);
                    float2 p0 = __half22float2(*(__half2*)&u.x);
                    float2 p1 = __half22float2(*(__half2*)&u.y);
                    float2 p2 = __half22float2(*(__half2*)&u.z);
                    float2 p3 = __half22float2(*(__half2*)&u.w);
                    f[0] = p0.x; f[1] = p0.y; f[2] = p1.x; f[3] = p1.y;
                    f[4] = p2.x; f[5] = p2.y; f[6] = p3.x; f[7] = p3.y;
                    #pragma unroll
                    for (int c = 0; c < 8; ++c)
                        f[c] = elu1(fmaf(f[c], scp[k0 + c], shp[k0 + c]));
                }
                uint32_t hp[4];
                #pragma unroll
                for (int p = 0; p < 4; ++p) {
                    __half2 h2 = __floats2half2_rn(f[p * 2], f[p * 2 + 1]);
                    hp[p] = *(uint32_t*)&h2;
                }
                *(int4*)(sm + SA + swz_off(row, kc)) = make_int4(hp[0], hp[1], hp[2], hp[3]);
            }
        } else {
            int4 z = make_int4(0, 0, 0, 0);
            #pragma unroll
            for (int c8 = 0; c8 < 8; ++c8)
                *(int4*)(sm + SA + swz_off(row, hq * 8 + c8)) = z;
        }
        __syncthreads();

        float acc[2][8][4];
        #pragma unroll
        for (int i = 0; i < 2; ++i)
            #pragma unroll
            for (int j = 0; j < 8; ++j)
                #pragma unroll
                for (int c = 0; c < 4; ++c) acc[i][j][c] = 0.f;

        #pragma unroll
        for (int ks = 0; ks < 8; ++ks) {
            int a_kc = ks * 2 + a_cadd;
            int b_kc = ks * 2 + b_cadd;

            uint32_t a[2][4];
            #pragma unroll
            for (int mf = 0; mf < 2; ++mf)
                ldsm4(a[mf][0], a[mf][1], a[mf][2], a[mf][3],
                      aB + swz_off(a_r0 + mf * 16, a_kc));

            uint32_t b[8][2];
            #pragma unroll
            for (int p = 0; p < 4; ++p)
                ldsm4(b[p * 2][0], b[p * 2][1], b[p * 2 + 1][0], b[p * 2 + 1][1],
                      bB + swz_off(warp_n + p * 16 + b_nsel, b_kc));

            #pragma unroll
            for (int mf = 0; mf < 2; ++mf)
                #pragma unroll
                for (int nf = 0; nf < 8; ++nf)
                    mma16816(acc[mf][nf], a[mf], b[nf]);
        }

        // --- epilogue: scale by dinv, convert fp16, store
        int qr = lane >> 2, qc = (lane & 3) * 2;
        #pragma unroll
        for (int mf = 0; mf < 2; ++mf) {
            int r0 = tile * 128 + warp_m + mf * 16 + qr;
            int r1 = r0 + 8;
            float d0 = (r0 < NN) ? g_dinv[r0] : 0.f;
            float d1 = (r1 < NN) ? g_dinv[r1] : 0.f;
            #pragma unroll
            for (int nf = 0; nf < 8; ++nf) {
                int col = warp_n + nf * 8 + qc;
                if (r0 < NN) {
                    __half2 o = __floats2half2_rn(acc[mf][nf][0] * d0, acc[mf][nf][1] * d0);
                    *(__half2*)(g_gbuf + (size_t)r0 * DH + col) = o;
                }
                if (r1 < NN) {
                    __half2 o = __floats2half2_rn(acc[mf][nf][2] * d1, acc[mf][nf][3] * d1);
                    *(__half2*)(g_gbuf + (size_t)r1 * DH + col) = o;
                }
            }
        }
        __syncthreads();   // all mainloop reads done before next tile rewrites SA
    }
}

// ---------------- aggregation: fp16 gather (MLP 8), fp32 accum, fp16 h ------
__device__ __forceinline__ void add_h4(float4& a, uint2 u) {
    float2 p0 = __half22float2(*(__half2*)&u.x);
    float2 p1 = __half22float2(*(__half2*)&u.y);
    a.x += p0.x; a.y += p0.y; a.z += p1.x; a.w += p1.y;
}

__global__ void __launch_bounds__(256) k_agg(int layer, const float* __restrict__ bias,
                                             float* __restrict__ out) {
    if (out) {
        int idx = blockIdx.x * 256 + threadIdx.x;
        if (idx < NG * DH) out[idx] = 0.f;
    }
    __shared__ float s_sum[DH];
    __shared__ float s_sq[DH];
    int tid = threadIdx.x;
    if (tid < DH) { s_sum[tid] = 0.f; s_sq[tid] = 0.f; }
    __syncthreads();

    int warp = tid >> 5, lane = tid & 31;
    int base = blockIdx.x * 32 + warp * 4;
    int f = lane * 4;
    float4 b = ((const float4*)bias)[lane];

    float ls0 = 0.f, ls1 = 0.f, ls2 = 0.f, ls3 = 0.f;
    float lq0 = 0.f, lq1 = 0.f, lq2 = 0.f, lq3 = 0.f;

    int nend = base + 4 < NN ? base + 4 : NN;
    for (int node = base; node < nend; ++node) {
        float4 a0 = make_float4(0.f, 0.f, 0.f, 0.f);
        float4 a1 = make_float4(0.f, 0.f, 0.f, 0.f);
        add_h4(a0, *(const uint2*)(g_gbuf + (size_t)node * DH + f));   // self
        int s = g_off[node], e2 = g_off[node + 1];
        int p = s;
        for (; p + 7 < e2; p += 8) {
            int i0 = g_csr[p],     i1 = g_csr[p + 1], i2 = g_csr[p + 2], i3 = g_csr[p + 3];
            int i4 = g_csr[p + 4], i5 = g_csr[p + 5], i6 = g_csr[p + 6], i7 = g_csr[p + 7];
            uint2 u0 = *(const uint2*)(g_gbuf + (size_t)i0 * DH + f);
            uint2 u1 = *(const uint2*)(g_gbuf + (size_t)i1 * DH + f);
            uint2 u2 = *(const uint2*)(g_gbuf + (size_t)i2 * DH + f);
            uint2 u3 = *(const uint2*)(g_gbuf + (size_t)i3 * DH + f);
            uint2 u4 = *(const uint2*)(g_gbuf + (size_t)i4 * DH + f);
            uint2 u5 = *(const uint2*)(g_gbuf + (size_t)i5 * DH + f);
            uint2 u6 = *(const uint2*)(g_gbuf + (size_t)i6 * DH + f);
            uint2 u7 = *(const uint2*)(g_gbuf + (size_t)i7 * DH + f);
            add_h4(a0, u0); add_h4(a1, u1); add_h4(a0, u2); add_h4(a1, u3);
            add_h4(a0, u4); add_h4(a1, u5); add_h4(a0, u6); add_h4(a1, u7);
        }
        for (; p + 1 < e2; p += 2) {
            int i0 = g_csr[p], i1 = g_csr[p + 1];
            uint2 u0 = *(const uint2*)(g_gbuf + (size_t)i0 * DH + f);
            uint2 u1 = *(const uint2*)(g_gbuf + (size_t)i1 * DH + f);
            add_h4(a0, u0); add_h4(a1, u1);
        }
        if (p < e2) {
            int i0 = g_csr[p];
            add_h4(a0, *(const uint2*)(g_gbuf + (size_t)i0 * DH + f));
        }
        float di = g_dinv[node];
        float4 h;
        h.x = fmaf(di, a0.x + a1.x, b.x);
        h.y = fmaf(di, a0.y + a1.y, b.y);
        h.z = fmaf(di, a0.z + a1.z, b.z);
        h.w = fmaf(di, a0.w + a1.w, b.w);
        __half2 o0 = __floats2half2_rn(h.x, h.y);
        __half2 o1 = __floats2half2_rn(h.z, h.w);
        uint2 ov;
        ov.x = *(uint32_t*)&o0;
        ov.y = *(uint32_t*)&o1;
        *(uint2*)(g_hag + (size_t)node * DH + f) = ov;

        ls0 += h.x; lq0 += h.x * h.x;
        ls1 += h.y; lq1 += h.y * h.y;
        ls2 += h.z; lq2 += h.z * h.z;
        ls3 += h.w; lq3 += h.w * h.w;
    }
    atomicAdd(&s_sum[f + 0], ls0); atomicAdd(&s_sq[f + 0], lq0);
    atomicAdd(&s_sum[f + 1], ls1); atomicAdd(&s_sq[f + 1], lq1);
    atomicAdd(&s_sum[f + 2], ls2); atomicAdd(&s_sq[f + 2], lq2);
    atomicAdd(&s_sum[f + 3], ls3); atomicAdd(&s_sq[f + 3], lq3);
    __syncthreads();
    if (tid < DH) {
        atomicAdd(&g_sum[layer * DH + tid], s_sum[tid]);
        atomicAdd(&g_sq[layer * DH + tid], s_sq[tid]);
    }
}

// ---------------- pooling: batch-preloaded rows, pre-scaled atomics ----------
__global__ void __launch_bounds__(256) k_pool(const int* __restrict__ bidx,
                                              const float* __restrict__ gamma,
                                              const float* __restrict__ beta,
                                              float* __restrict__ out) {
    int tid = threadIdx.x;
    int warp = (blockIdx.x * 8 + (tid >> 5));
    int base = warp * 8;
    if (base >= NN) return;
    int lane = tid & 31;
    int f = lane * 4;
    const int L2 = (NL - 1) * DH;
    float s[4], t[4];
    #pragma unroll
    for (int c = 0; c < 4; ++c) {
        float m = g_sum[L2 + f + c] * (1.f / NN);
        float var = g_sq[L2 + f + c] * (1.f / NN) - m * m;
        float rs = rsqrtf(var + BN_EPS);
        s[c] = gamma[f + c] * rs;
        t[c] = beta[f + c] - m * s[c];
    }

    int cnt = base + 8 < NN ? 8 : NN - base;
    uint2 r[8];
    int bi[8];
    #pragma unroll
    for (int i = 0; i < 8; ++i) {
        if (i < cnt) {
            r[i] = *(const uint2*)(g_hag + (size_t)(base + i) * DH + f);
            bi[i] = bidx[base + i];
        }
    }

    float a0 = 0.f, a1 = 0.f, a2 = 0.f, a3 = 0.f;
    int cur = bi[0];
    #pragma unroll
    for (int i = 0; i < 8; ++i) {
        if (i >= cnt) break;
        if (bi[i] != cur) {
            float inv = 1.f / fmaxf((float)g_cnt[cur], 1.f);
            float* o = out + (size_t)cur * DH + f;
            atomicAdd(o + 0, a0 * inv); atomicAdd(o + 1, a1 * inv);
            atomicAdd(o + 2, a2 * inv); atomicAdd(o + 3, a3 * inv);
            a0 = a1 = a2 = a3 = 0.f;
            cur = bi[i];
        }
        float2 p0 = __half22float2(*(__half2*)&r[i].x);
        float2 p1 = __half22float2(*(__half2*)&r[i].y);
        a0 += elu1(fmaf(p0.x, s[0], t[0]));
        a1 += elu1(fmaf(p0.y, s[1], t[1]));
        a2 += elu1(fmaf(p1.x, s[2], t[2]));
        a3 += elu1(fmaf(p1.y, s[3], t[3]));
    }
    float inv = 1.f / fmaxf((float)g_cnt[cur], 1.f);
    float* o = out + (size_t)cur * DH + f;
    atomicAdd(o + 0, a0 * inv); atomicAdd(o + 1, a1 * inv);
    atomicAdd(o + 2, a2 * inv); atomicAdd(o + 3, a3 * inv);
}

// ---------------- launch ----------------
extern "C" void kernel_launch(void* const* d_in, const int* in_sizes, int n_in,
                              void* d_out, int out_size) {
    const float* x      = (const float*)d_in[0];
    const float* Ws     = (const float*)d_in[1];
    const float* bs     = (const float*)d_in[2];
    const float* gammas = (const float*)d_in[3];
    const float* betas  = (const float*)d_in[4];
    const int*   ei     = (const int*)d_in[5];
    const int*   bidx   = (const int*)d_in[6];
    float*       out    = (float*)d_out;

    const int* src = ei;
    const int* dst = ei + NE;

    cudaFuncSetAttribute(k_gemm_tc, cudaFuncAttributeMaxDynamicSharedMemorySize, SM_TOTAL);

    int agg_grid = (NN + 31) / 32;

    k_init_all<<<(NN + 255) / 256, 256>>>(Ws);                      // 1
    k_deg<<<(NE + 255) / 256, 256>>>(dst, bidx);                    // 2
    k_bsum<<<SCAN_NB, SCAN_T>>>();                                  // 3 (+dinv)
    k_gemm_tc<<<GEMM_GRID, 256, SM_TOTAL>>>(0, x, gammas, betas);   // 4 <- ncu slot
    k_lscan<<<SCAN_NB, SCAN_T>>>();                                 // 5 (+bscan)
    k_fill<<<(NE + 255) / 256, 256>>>(src, dst);                    // 6

    k_agg<<<agg_grid, 256>>>(0, bs, nullptr);                       // 7
    k_gemm_tc<<<GEMM_GRID, 256, SM_TOTAL>>>(1, x, gammas + DH, betas + DH);
    k_agg<<<agg_grid, 256>>>(1, bs + DH, nullptr);
    k_gemm_tc<<<GEMM_GRID, 256, SM_TOTAL>>>(2, x, gammas + 2 * DH, betas + 2 * DH);
    k_agg<<<agg_grid, 256>>>(2, bs + 2 * DH, out);                  // zeroes out

    int pool_grid = (NN + 63) / 64;
    k_pool<<<pool_grid, 256>>>(bidx, gammas + 2 * DH, betas + 2 * DH, out);
}